// round 1
// baseline (speedup 1.0000x reference)
#include <cuda_runtime.h>
#include <cuda_bf16.h>
#include <math.h>

// Problem constants
#define BATCH 4
#define SEQ   4096
#define DM    1024          // d_model
#define DI    2048          // d_inner
#define DS    16            // d_state
#define NTOK  (BATCH*SEQ)   // 16384
#define CHUNK 128
#define NCHUNK (SEQ/CHUNK)  // 32

// Scratch (device globals — no allocations allowed)
__device__ float g_XR[NTOK * 2 * DI];   // 256 MB : [x_main | res]
__device__ float g_XC[NTOK * DI];       // 128 MB : conv+silu output
__device__ float g_Y [NTOK * DI];       // 128 MB : gated pre-out
__device__ float g_BT[NTOK * DS];       // 1 MB
__device__ float g_CT[NTOK * DS];       // 1 MB
__device__ float g_S [BATCH * NCHUNK * DS];   // chunk summaries
__device__ float g_CAR[BATCH * NCHUNK * DS];  // chunk carry-in states
__device__ float g_YS[NTOK];            // scan scalar output

// ---------------------------------------------------------------------------
// Generic fp32 SGEMM: C = A(MxK) * B(KxN), all row-major.
// BM=BN=128, BK=8, 256 threads, 8x8 per-thread microtile. Dims must be
// multiples of the tiles (they are: M=16384, N in {4096,1024}, K in {1024,2048}).
// ---------------------------------------------------------------------------
__global__ __launch_bounds__(256, 2)
void sgemm128(const float* __restrict__ Ag, const float* __restrict__ Bg,
              float* __restrict__ Cg, int M, int N, int K) {
    __shared__ float As[8][128];
    __shared__ float Bs[8][128];

    const int tid  = threadIdx.x;
    const int brow = blockIdx.y;
    const int bcol = blockIdx.x;

    // A tile load mapping: 128 rows x 8 k -> one float4 per thread
    const int arow = tid >> 1;            // 0..127
    const int acol = (tid & 1) * 4;       // 0 or 4
    // B tile load mapping: 8 k x 128 cols -> one float4 per thread
    const int bkr  = tid >> 5;            // 0..7
    const int bcl  = (tid & 31) * 4;      // 0..124

    const float* Aptr = Ag + (size_t)(brow * 128 + arow) * K + acol;
    const float* Bptr = Bg + (size_t)bkr * N + bcol * 128 + bcl;

    const int ty = tid >> 4;   // 0..15 -> rows ty*8..ty*8+7
    const int tx = tid & 15;   // 0..15 -> cols tx*8..tx*8+7

    float acc[8][8];
#pragma unroll
    for (int i = 0; i < 8; i++)
#pragma unroll
        for (int j = 0; j < 8; j++) acc[i][j] = 0.f;

    for (int k0 = 0; k0 < K; k0 += 8) {
        float4 a4 = *(const float4*)Aptr;  Aptr += 8;
        float4 b4 = *(const float4*)Bptr;  Bptr += (size_t)8 * N;

        As[acol + 0][arow] = a4.x;
        As[acol + 1][arow] = a4.y;
        As[acol + 2][arow] = a4.z;
        As[acol + 3][arow] = a4.w;
        *(float4*)&Bs[bkr][bcl] = b4;
        __syncthreads();

#pragma unroll
        for (int k = 0; k < 8; k++) {
            float ra[8], rb[8];
#pragma unroll
            for (int i = 0; i < 8; i++) ra[i] = As[k][ty * 8 + i];
#pragma unroll
            for (int j = 0; j < 8; j++) rb[j] = Bs[k][tx * 8 + j];
#pragma unroll
            for (int i = 0; i < 8; i++)
#pragma unroll
                for (int j = 0; j < 8; j++)
                    acc[i][j] = fmaf(ra[i], rb[j], acc[i][j]);
        }
        __syncthreads();
    }

#pragma unroll
    for (int i = 0; i < 8; i++) {
        float* crow = Cg + (size_t)(brow * 128 + ty * 8 + i) * N + bcol * 128 + tx * 8;
        *(float4*)(crow + 0) = make_float4(acc[i][0], acc[i][1], acc[i][2], acc[i][3]);
        *(float4*)(crow + 4) = make_float4(acc[i][4], acc[i][5], acc[i][6], acc[i][7]);
    }
}

// ---------------------------------------------------------------------------
// Depthwise conv(3, pad 1) + bias + SiLU.  x_main = first DI cols of XR.
// ---------------------------------------------------------------------------
__global__ void conv_silu(const float* __restrict__ conv_w,
                          const float* __restrict__ conv_b) {
    int idx = blockIdx.x * blockDim.x + threadIdx.x;   // over NTOK*DI
    if (idx >= NTOK * DI) return;
    int i  = idx & (DI - 1);
    int bt = idx >> 11;          // /DI
    int t  = bt & (SEQ - 1);

    const float w0 = conv_w[i * 3 + 0];
    const float w1 = conv_w[i * 3 + 1];
    const float w2 = conv_w[i * 3 + 2];

    float xm1 = (t > 0)       ? g_XR[(size_t)(bt - 1) * (2 * DI) + i] : 0.f;
    float x0  =                 g_XR[(size_t)bt       * (2 * DI) + i];
    float xp1 = (t < SEQ - 1) ? g_XR[(size_t)(bt + 1) * (2 * DI) + i] : 0.f;

    float v = fmaf(w0, xm1, fmaf(w1, x0, fmaf(w2, xp1, conv_b[i])));
    v = v / (1.f + expf(-v));   // silu
    g_XC[idx] = v;
}

// ---------------------------------------------------------------------------
// B/C projections: BT = XC @ W_B, CT = XC @ W_C   (NTOK x 16 each)
// block = 32 rows, 256 threads: thread -> (row r, group g); g<4 -> B cols, g>=4 -> C cols
// ---------------------------------------------------------------------------
__global__ __launch_bounds__(256)
void bc_gemm(const float* __restrict__ WB, const float* __restrict__ WC) {
    __shared__ float sh[32][33];
    const int row0 = blockIdx.x * 32;
    const int r = threadIdx.x & 31;
    const int g = threadIdx.x >> 5;          // 0..7
    const float* __restrict__ W = (g < 4) ? WB : WC;
    float* __restrict__ OUT = (g < 4) ? g_BT : g_CT;
    const int s0 = (g & 3) * 4;

    float acc[4] = {0.f, 0.f, 0.f, 0.f};

    const int lr  = threadIdx.x >> 3;        // 0..31 load row
    const int lk4 = (threadIdx.x & 7) * 4;   // 0..28 load k

    for (int k0 = 0; k0 < DI; k0 += 32) {
        float4 v = *(const float4*)&g_XC[(size_t)(row0 + lr) * DI + k0 + lk4];
        sh[lr][lk4 + 0] = v.x; sh[lr][lk4 + 1] = v.y;
        sh[lr][lk4 + 2] = v.z; sh[lr][lk4 + 3] = v.w;
        __syncthreads();
#pragma unroll 8
        for (int kk = 0; kk < 32; kk++) {
            float a = sh[r][kk];
            float4 w4 = *(const float4*)&W[(size_t)(k0 + kk) * DS + s0];
            acc[0] = fmaf(a, w4.x, acc[0]);
            acc[1] = fmaf(a, w4.y, acc[1]);
            acc[2] = fmaf(a, w4.z, acc[2]);
            acc[3] = fmaf(a, w4.w, acc[3]);
        }
        __syncthreads();
    }
#pragma unroll
    for (int j = 0; j < 4; j++)
        OUT[(size_t)(row0 + r) * DS + s0 + j] = acc[j];
}

// ---------------------------------------------------------------------------
// Scan phase 1: per (b, chunk, s) weighted chunk sum  S = sum decay^(L-1-j) B[j]
// ---------------------------------------------------------------------------
__global__ void scan_chunk(const float* __restrict__ A) {
    int idx = blockIdx.x * blockDim.x + threadIdx.x;
    if (idx >= BATCH * NCHUNK * DS) return;
    int s = idx & (DS - 1);
    int c = (idx >> 4) & (NCHUNK - 1);
    int b = idx >> 9;
    float d = 1.f / (1.f + expf(A[s]));   // exp(-softplus(A)) = sigmoid(-A)
    float acc = 0.f;
    size_t base = ((size_t)b * SEQ + (size_t)c * CHUNK) * DS + s;
#pragma unroll 4
    for (int j = 0; j < CHUNK; j++)
        acc = fmaf(acc, d, g_BT[base + (size_t)j * DS]);
    g_S[idx] = acc;
}

// Scan phase 2: sequential carry across chunks (64 threads)
__global__ void scan_carry(const float* __restrict__ A) {
    int idx = threadIdx.x;
    if (idx >= BATCH * DS) return;
    int s = idx & (DS - 1);
    int b = idx >> 4;
    float d = 1.f / (1.f + expf(A[s]));
    // d^128 via 7 squarings
    float dL = d;
#pragma unroll
    for (int q = 0; q < 7; q++) dL = dL * dL;
    float cur = 0.f;
    for (int c = 0; c < NCHUNK; c++) {
        int off = ((b * NCHUNK) + c) * DS + s;
        g_CAR[off] = cur;
        cur = fmaf(cur, dL, g_S[off]);
    }
}

// Scan phase 3: replay each chunk with its carry-in, emit ys
__global__ void scan_ys(const float* __restrict__ A) {
    int bc = blockIdx.x;               // 0..127
    int b = bc >> 5, c = bc & 31;
    int lane = threadIdx.x;            // 32
    int s = lane & (DS - 1);
    float d = 1.f / (1.f + expf(A[s]));
    float state = (lane < DS) ? g_CAR[bc * DS + s] : 0.f;
    size_t base = ((size_t)b * SEQ + (size_t)c * CHUNK) * DS + s;
    int tout = b * SEQ + c * CHUNK;
    for (int j = 0; j < CHUNK; j++) {
        float v = 0.f;
        if (lane < DS) {
            size_t off = base + (size_t)j * DS;
            state = fmaf(state, d, g_BT[off]);
            v = state * g_CT[off];
        }
        v += __shfl_xor_sync(0xffffffffu, v, 8);
        v += __shfl_xor_sync(0xffffffffu, v, 4);
        v += __shfl_xor_sync(0xffffffffu, v, 2);
        v += __shfl_xor_sync(0xffffffffu, v, 1);
        if (lane == 0) g_YS[tout + j] = v;
    }
}

// ---------------------------------------------------------------------------
// Gate: Y = (ys + xc*D) * silu(res)
// ---------------------------------------------------------------------------
__global__ void ygate(const float* __restrict__ Dp) {
    int idx = blockIdx.x * blockDim.x + threadIdx.x;
    if (idx >= NTOK * DI) return;
    int i  = idx & (DI - 1);
    int bt = idx >> 11;
    float res = g_XR[(size_t)bt * (2 * DI) + DI + i];
    float sres = res / (1.f + expf(-res));
    float v = fmaf(g_XC[idx], Dp[i], g_YS[bt]);
    g_Y[idx] = v * sres;
}

// ---------------------------------------------------------------------------
extern "C" void kernel_launch(void* const* d_in, const int* in_sizes, int n_in,
                              void* d_out, int out_size) {
    const float* x      = (const float*)d_in[0];
    const float* W_in   = (const float*)d_in[1];
    const float* conv_w = (const float*)d_in[2];
    const float* conv_b = (const float*)d_in[3];
    const float* W_B    = (const float*)d_in[4];
    const float* W_C    = (const float*)d_in[5];
    const float* A      = (const float*)d_in[6];
    const float* D      = (const float*)d_in[7];
    const float* W_out  = (const float*)d_in[8];
    float* out = (float*)d_out;

    float* XR; cudaGetSymbolAddress((void**)&XR, g_XR);
    float* Y;  cudaGetSymbolAddress((void**)&Y,  g_Y);

    // 1) xr = x @ W_in   (16384 x 4096 x 1024)
    {
        dim3 grid((2 * DI) / 128, NTOK / 128);
        sgemm128<<<grid, 256>>>(x, W_in, XR, NTOK, 2 * DI, DM);
    }
    // 2) depthwise conv + silu
    conv_silu<<<(NTOK * DI) / 256, 256>>>(conv_w, conv_b);
    // 3) B/C projections
    bc_gemm<<<NTOK / 32, 256>>>(W_B, W_C);
    // 4) scan
    scan_chunk<<<(BATCH * NCHUNK * DS + 255) / 256, 256>>>(A);
    scan_carry<<<1, 64>>>(A);
    scan_ys<<<BATCH * NCHUNK, 32>>>(A);
    // 5) gate
    ygate<<<(NTOK * DI) / 256, 256>>>(D);
    // 6) out = Y @ W_out   (16384 x 1024 x 2048)
    {
        dim3 grid(DM / 128, NTOK / 128);
        sgemm128<<<grid, 256>>>(Y, W_out, out, NTOK, DM, DI);
    }
}

// round 5
// speedup vs baseline: 3.5936x; 3.5936x over previous
#include <cuda_runtime.h>
#include <cuda_bf16.h>
#include <cstdint>
#include <math.h>

// Problem constants
#define BATCH 4
#define SEQ   4096
#define DM    1024          // d_model
#define DI    2048          // d_inner
#define DS    16            // d_state
#define NTOK  (BATCH*SEQ)   // 16384
#define CHUNK 128
#define NCHUNK (SEQ/CHUNK)  // 32

// Scratch (device globals — no allocations allowed)
__device__ float g_XR[NTOK * 2 * DI];   // 256 MB : [x_main | res]
__device__ float g_XC[NTOK * DI];       // 128 MB : conv+silu output
__device__ float g_Y [NTOK * DI];       // 128 MB : gated pre-out
__device__ float g_BT[NTOK * DS];       // 1 MB
__device__ float g_CT[NTOK * DS];       // 1 MB
__device__ float g_S [BATCH * NCHUNK * DS];   // chunk summaries
__device__ float g_CAR[BATCH * NCHUNK * DS];  // chunk carry-in states
__device__ float g_YS[NTOK];            // scan scalar output

// ---------------------------------------------------------------------------
// TF32 tensor-core GEMM: C = A(MxK) * B(KxN), row-major fp32 in/out.
// CTA tile 128x128, BK=32, 256 threads (8 warps, 2x4), warp tile 64x32.
// mma.sync.aligned.m16n8k8.row.col.f32.tf32.tf32.f32
// Double-buffered smem; A pad-stride 36 (conflict-free frag loads), B 132.
// ---------------------------------------------------------------------------
#define A_STRIDE 36
#define B_STRIDE 132
#define SMEM_A_ELE (2 * 128 * A_STRIDE)
#define SMEM_B_ELE (2 * 32  * B_STRIDE)
#define GEMM_SMEM_BYTES ((SMEM_A_ELE + SMEM_B_ELE) * 4)

__device__ __forceinline__ unsigned int f2tf32(float x) {
    unsigned int r;
    asm("cvt.rna.tf32.f32 %0, %1;" : "=r"(r) : "f"(x));
    return r;
}

__device__ __forceinline__ void mma_tf32(float* d, const unsigned int* a, const unsigned int* b) {
    asm volatile(
        "mma.sync.aligned.m16n8k8.row.col.f32.tf32.tf32.f32 "
        "{%0,%1,%2,%3},{%4,%5,%6,%7},{%8,%9},{%0,%1,%2,%3};"
        : "+f"(d[0]), "+f"(d[1]), "+f"(d[2]), "+f"(d[3])
        : "r"(a[0]), "r"(a[1]), "r"(a[2]), "r"(a[3]), "r"(b[0]), "r"(b[1]));
}

__global__ __launch_bounds__(256)
void gemm_tf32(const float* __restrict__ Ag, const float* __restrict__ Bg,
               float* __restrict__ Cg, int M, int N, int K) {
    extern __shared__ float sm[];
    float* As = sm;                     // [2][128][A_STRIDE]
    float* Bs = sm + SMEM_A_ELE;        // [2][32][B_STRIDE]

    const int tid  = threadIdx.x;
    const int lane = tid & 31;
    const int warp = tid >> 5;
    const int wm   = warp >> 2;         // 0..1 -> rows wm*64
    const int wn   = warp & 3;          // 0..3 -> cols wn*32
    const int brow = blockIdx.y * 128;
    const int bcol = blockIdx.x * 128;

    // global load mapping
    const int ar = tid >> 3;            // A row 0..31 (+32i)
    const int ac = (tid & 7) * 4;       // A col 0..28
    const int br = tid >> 5;            // B row 0..7 (+8i)
    const int bc = (tid & 31) * 4;      // B col 0..124

    const float* Ap = Ag + (size_t)(brow + ar) * K + ac;
    const float* Bp = Bg + (size_t)br * N + bcol + bc;

    const int lq = lane >> 2;           // 0..7
    const int lr = lane & 3;            // 0..3

    float4 ra[4], rb[4];
    float acc[4][4][4];
#pragma unroll
    for (int mt = 0; mt < 4; mt++)
#pragma unroll
        for (int nt = 0; nt < 4; nt++)
#pragma unroll
            for (int e = 0; e < 4; e++) acc[mt][nt][e] = 0.f;

    const int nit = K >> 5;

    // prologue: load tile 0
#pragma unroll
    for (int i = 0; i < 4; i++) ra[i] = *(const float4*)(Ap + (size_t)(32 * i) * K);
#pragma unroll
    for (int i = 0; i < 4; i++) rb[i] = *(const float4*)(Bp + (size_t)(8 * i) * N);
    Ap += 32; Bp += (size_t)32 * N;

#pragma unroll
    for (int i = 0; i < 4; i++) {
        float* p = &As[(size_t)(ar + 32 * i) * A_STRIDE + ac];
        p[0] = __uint_as_float(f2tf32(ra[i].x));
        p[1] = __uint_as_float(f2tf32(ra[i].y));
        p[2] = __uint_as_float(f2tf32(ra[i].z));
        p[3] = __uint_as_float(f2tf32(ra[i].w));
    }
#pragma unroll
    for (int i = 0; i < 4; i++) {
        float* p = &Bs[(size_t)(br + 8 * i) * B_STRIDE + bc];
        p[0] = __uint_as_float(f2tf32(rb[i].x));
        p[1] = __uint_as_float(f2tf32(rb[i].y));
        p[2] = __uint_as_float(f2tf32(rb[i].z));
        p[3] = __uint_as_float(f2tf32(rb[i].w));
    }
    __syncthreads();

    for (int it = 0; it < nit; it++) {
        if (it + 1 < nit) {
#pragma unroll
            for (int i = 0; i < 4; i++) ra[i] = *(const float4*)(Ap + (size_t)(32 * i) * K);
#pragma unroll
            for (int i = 0; i < 4; i++) rb[i] = *(const float4*)(Bp + (size_t)(8 * i) * N);
            Ap += 32; Bp += (size_t)32 * N;
        }

        const float* Ab = As + (size_t)(it & 1) * 128 * A_STRIDE;
        const float* Bb = Bs + (size_t)(it & 1) * 32 * B_STRIDE;

#pragma unroll
        for (int ks = 0; ks < 4; ks++) {
            const int k = ks * 8;
            unsigned int af[4][4], bf[4][2];
#pragma unroll
            for (int mt = 0; mt < 4; mt++) {
                const float* p = Ab + (size_t)(wm * 64 + mt * 16 + lq) * A_STRIDE + k + lr;
                af[mt][0] = __float_as_uint(p[0]);
                af[mt][1] = __float_as_uint(p[8 * A_STRIDE]);
                af[mt][2] = __float_as_uint(p[4]);
                af[mt][3] = __float_as_uint(p[8 * A_STRIDE + 4]);
            }
#pragma unroll
            for (int nt = 0; nt < 4; nt++) {
                const float* p = Bb + (size_t)(k + lr) * B_STRIDE + wn * 32 + nt * 8 + lq;
                bf[nt][0] = __float_as_uint(p[0]);
                bf[nt][1] = __float_as_uint(p[4 * B_STRIDE]);
            }
#pragma unroll
            for (int mt = 0; mt < 4; mt++)
#pragma unroll
                for (int nt = 0; nt < 4; nt++)
                    mma_tf32(acc[mt][nt], af[mt], bf[nt]);
        }

        if (it + 1 < nit) {
            float* Aw = As + (size_t)((it + 1) & 1) * 128 * A_STRIDE;
            float* Bw = Bs + (size_t)((it + 1) & 1) * 32 * B_STRIDE;
#pragma unroll
            for (int i = 0; i < 4; i++) {
                float* p = &Aw[(size_t)(ar + 32 * i) * A_STRIDE + ac];
                p[0] = __uint_as_float(f2tf32(ra[i].x));
                p[1] = __uint_as_float(f2tf32(ra[i].y));
                p[2] = __uint_as_float(f2tf32(ra[i].z));
                p[3] = __uint_as_float(f2tf32(ra[i].w));
            }
#pragma unroll
            for (int i = 0; i < 4; i++) {
                float* p = &Bw[(size_t)(br + 8 * i) * B_STRIDE + bc];
                p[0] = __uint_as_float(f2tf32(rb[i].x));
                p[1] = __uint_as_float(f2tf32(rb[i].y));
                p[2] = __uint_as_float(f2tf32(rb[i].z));
                p[3] = __uint_as_float(f2tf32(rb[i].w));
            }
            __syncthreads();
        }
    }

    // epilogue
#pragma unroll
    for (int mt = 0; mt < 4; mt++) {
        const int r0 = brow + wm * 64 + mt * 16 + lq;
#pragma unroll
        for (int nt = 0; nt < 4; nt++) {
            const int c0 = bcol + wn * 32 + nt * 8 + lr * 2;
            *(float2*)&Cg[(size_t)r0 * N + c0]       = make_float2(acc[mt][nt][0], acc[mt][nt][1]);
            *(float2*)&Cg[(size_t)(r0 + 8) * N + c0] = make_float2(acc[mt][nt][2], acc[mt][nt][3]);
        }
    }
}

// ---------------------------------------------------------------------------
// Depthwise conv(3, pad 1) + bias + SiLU.  x_main = first DI cols of XR.
// ---------------------------------------------------------------------------
__global__ void conv_silu(const float* __restrict__ conv_w,
                          const float* __restrict__ conv_b) {
    int idx = blockIdx.x * blockDim.x + threadIdx.x;   // over NTOK*DI
    if (idx >= NTOK * DI) return;
    int i  = idx & (DI - 1);
    int bt = idx >> 11;          // /DI
    int t  = bt & (SEQ - 1);

    const float w0 = conv_w[i * 3 + 0];
    const float w1 = conv_w[i * 3 + 1];
    const float w2 = conv_w[i * 3 + 2];

    float xm1 = (t > 0)       ? g_XR[(size_t)(bt - 1) * (2 * DI) + i] : 0.f;
    float x0  =                 g_XR[(size_t)bt       * (2 * DI) + i];
    float xp1 = (t < SEQ - 1) ? g_XR[(size_t)(bt + 1) * (2 * DI) + i] : 0.f;

    float v = fmaf(w0, xm1, fmaf(w1, x0, fmaf(w2, xp1, conv_b[i])));
    v = v / (1.f + expf(-v));   // silu
    g_XC[idx] = v;
}

// ---------------------------------------------------------------------------
// B/C projections: BT = XC @ W_B, CT = XC @ W_C   (NTOK x 16 each)
// ---------------------------------------------------------------------------
__global__ __launch_bounds__(256)
void bc_gemm(const float* __restrict__ WB, const float* __restrict__ WC) {
    __shared__ float sh[32][33];
    const int row0 = blockIdx.x * 32;
    const int r = threadIdx.x & 31;
    const int g = threadIdx.x >> 5;          // 0..7
    const float* __restrict__ W = (g < 4) ? WB : WC;
    float* __restrict__ OUT = (g < 4) ? g_BT : g_CT;
    const int s0 = (g & 3) * 4;

    float acc[4] = {0.f, 0.f, 0.f, 0.f};

    const int lr  = threadIdx.x >> 3;        // 0..31 load row
    const int lk4 = (threadIdx.x & 7) * 4;   // 0..28 load k

    for (int k0 = 0; k0 < DI; k0 += 32) {
        float4 v = *(const float4*)&g_XC[(size_t)(row0 + lr) * DI + k0 + lk4];
        sh[lr][lk4 + 0] = v.x; sh[lr][lk4 + 1] = v.y;
        sh[lr][lk4 + 2] = v.z; sh[lr][lk4 + 3] = v.w;
        __syncthreads();
#pragma unroll 8
        for (int kk = 0; kk < 32; kk++) {
            float a = sh[r][kk];
            float4 w4 = *(const float4*)&W[(size_t)(k0 + kk) * DS + s0];
            acc[0] = fmaf(a, w4.x, acc[0]);
            acc[1] = fmaf(a, w4.y, acc[1]);
            acc[2] = fmaf(a, w4.z, acc[2]);
            acc[3] = fmaf(a, w4.w, acc[3]);
        }
        __syncthreads();
    }
#pragma unroll
    for (int j = 0; j < 4; j++)
        OUT[(size_t)(row0 + r) * DS + s0 + j] = acc[j];
}

// ---------------------------------------------------------------------------
// Scan phase 1: per (b, chunk, s) weighted chunk sum
// ---------------------------------------------------------------------------
__global__ void scan_chunk(const float* __restrict__ A) {
    int idx = blockIdx.x * blockDim.x + threadIdx.x;
    if (idx >= BATCH * NCHUNK * DS) return;
    int s = idx & (DS - 1);
    int c = (idx >> 4) & (NCHUNK - 1);
    int b = idx >> 9;
    float d = 1.f / (1.f + expf(A[s]));   // exp(-softplus(A)) = sigmoid(-A)
    float acc = 0.f;
    size_t base = ((size_t)b * SEQ + (size_t)c * CHUNK) * DS + s;
#pragma unroll 4
    for (int j = 0; j < CHUNK; j++)
        acc = fmaf(acc, d, g_BT[base + (size_t)j * DS]);
    g_S[idx] = acc;
}

// Scan phase 2: sequential carry across chunks (64 threads)
__global__ void scan_carry(const float* __restrict__ A) {
    int idx = threadIdx.x;
    if (idx >= BATCH * DS) return;
    int s = idx & (DS - 1);
    int b = idx >> 4;
    float d = 1.f / (1.f + expf(A[s]));
    float dL = d;
#pragma unroll
    for (int q = 0; q < 7; q++) dL = dL * dL;
    float cur = 0.f;
    for (int c = 0; c < NCHUNK; c++) {
        int off = ((b * NCHUNK) + c) * DS + s;
        g_CAR[off] = cur;
        cur = fmaf(cur, dL, g_S[off]);
    }
}

// Scan phase 3: replay each chunk with its carry-in, emit ys
__global__ void scan_ys(const float* __restrict__ A) {
    int bc = blockIdx.x;               // 0..127
    int b = bc >> 5, c = bc & 31;
    int lane = threadIdx.x;            // 32
    int s = lane & (DS - 1);
    float d = 1.f / (1.f + expf(A[s]));
    float state = (lane < DS) ? g_CAR[bc * DS + s] : 0.f;
    size_t base = ((size_t)b * SEQ + (size_t)c * CHUNK) * DS + s;
    int tout = b * SEQ + c * CHUNK;
    for (int j = 0; j < CHUNK; j++) {
        float v = 0.f;
        if (lane < DS) {
            size_t off = base + (size_t)j * DS;
            state = fmaf(state, d, g_BT[off]);
            v = state * g_CT[off];
        }
        v += __shfl_xor_sync(0xffffffffu, v, 8);
        v += __shfl_xor_sync(0xffffffffu, v, 4);
        v += __shfl_xor_sync(0xffffffffu, v, 2);
        v += __shfl_xor_sync(0xffffffffu, v, 1);
        if (lane == 0) g_YS[tout + j] = v;
    }
}

// ---------------------------------------------------------------------------
// Gate: Y = (ys + xc*D) * silu(res)
// ---------------------------------------------------------------------------
__global__ void ygate(const float* __restrict__ Dp) {
    int idx = blockIdx.x * blockDim.x + threadIdx.x;
    if (idx >= NTOK * DI) return;
    int i  = idx & (DI - 1);
    int bt = idx >> 11;
    float res = g_XR[(size_t)bt * (2 * DI) + DI + i];
    float sres = res / (1.f + expf(-res));
    float v = fmaf(g_XC[idx], Dp[i], g_YS[bt]);
    g_Y[idx] = v * sres;
}

// ---------------------------------------------------------------------------
extern "C" void kernel_launch(void* const* d_in, const int* in_sizes, int n_in,
                              void* d_out, int out_size) {
    const float* x      = (const float*)d_in[0];
    const float* W_in   = (const float*)d_in[1];
    const float* conv_w = (const float*)d_in[2];
    const float* conv_b = (const float*)d_in[3];
    const float* W_B    = (const float*)d_in[4];
    const float* W_C    = (const float*)d_in[5];
    const float* A      = (const float*)d_in[6];
    const float* D      = (const float*)d_in[7];
    const float* W_out  = (const float*)d_in[8];
    float* out = (float*)d_out;

    float* XR; cudaGetSymbolAddress((void**)&XR, g_XR);
    float* Y;  cudaGetSymbolAddress((void**)&Y,  g_Y);

    static bool attr_set = false;
    if (!attr_set) {
        cudaFuncSetAttribute(gemm_tf32, cudaFuncAttributeMaxDynamicSharedMemorySize,
                             GEMM_SMEM_BYTES);
        attr_set = true;
    }

    // 1) xr = x @ W_in   (16384 x 4096 x 1024)
    {
        dim3 grid((2 * DI) / 128, NTOK / 128);
        gemm_tf32<<<grid, 256, GEMM_SMEM_BYTES>>>(x, W_in, XR, NTOK, 2 * DI, DM);
    }
    // 2) depthwise conv + silu
    conv_silu<<<(NTOK * DI) / 256, 256>>>(conv_w, conv_b);
    // 3) B/C projections
    bc_gemm<<<NTOK / 32, 256>>>(W_B, W_C);
    // 4) scan
    scan_chunk<<<(BATCH * NCHUNK * DS + 255) / 256, 256>>>(A);
    scan_carry<<<1, 64>>>(A);
    scan_ys<<<BATCH * NCHUNK, 32>>>(A);
    // 5) gate
    ygate<<<(NTOK * DI) / 256, 256>>>(D);
    // 6) out = Y @ W_out   (16384 x 1024 x 2048)
    {
        dim3 grid(DM / 128, NTOK / 128);
        gemm_tf32<<<grid, 256, GEMM_SMEM_BYTES>>>(Y, W_out, out, NTOK, DM, DI);
    }
}

// round 7
// speedup vs baseline: 3.8397x; 1.0685x over previous
#include <cuda_runtime.h>
#include <cuda_bf16.h>
#include <cstdint>
#include <math.h>

// Problem constants
#define BATCH 4
#define SEQ   4096
#define DM    1024
#define DI    2048
#define DS    16
#define NTOK  (BATCH*SEQ)   // 16384
#define CHUNK 128
#define NCHUNK (SEQ/CHUNK)  // 32

// Scratch (device globals — no allocations allowed)
__device__ float g_XR[NTOK * 2 * DI];   // [x_main | res]
__device__ float g_XC[NTOK * DI];       // conv+silu output
__device__ float g_Y [NTOK * DI];       // gated pre-out (tf32-rounded)
__device__ float g_Xr[NTOK * DM];       // tf32-rounded x
__device__ float g_W1[DM * 2 * DI];     // tf32-rounded W_in
__device__ float g_W2[DI * DM];         // tf32-rounded W_out
__device__ float g_BT[NTOK * DS];
__device__ float g_CT[NTOK * DS];
__device__ float g_S [BATCH * NCHUNK * DS];
__device__ float g_CAR[BATCH * NCHUNK * DS];
__device__ float g_YS[NTOK];

__device__ __forceinline__ float f2tf32f(float x) {
    unsigned int r;
    asm("cvt.rna.tf32.f32 %0, %1;" : "=r"(r) : "f"(x));
    return __uint_as_float(r);
}

// ===========================================================================
// TF32 mma.sync GEMM with 4-stage cp.async pipeline.
// C = A(MxK) * B(KxN), row-major fp32 (inputs pre-rounded to tf32).
// CTA tile 128x128, BK=32, 256 threads (8 warps 2x4, warp tile 64x32).
// ===========================================================================
#define A_STRIDE 36
#define B_STRIDE 132
#define NSTAGE 4
#define STAGE_ELE (128 * A_STRIDE + 32 * B_STRIDE)   // 8832 floats
#define GEMM_SMEM_BYTES (NSTAGE * STAGE_ELE * 4)     // 141312 B

__device__ __forceinline__ uint32_t smem_u32(const void* p) {
    uint32_t a;
    asm("{ .reg .u64 t; cvta.to.shared.u64 t, %1; cvt.u32.u64 %0, t; }"
        : "=r"(a) : "l"(p));
    return a;
}
__device__ __forceinline__ void cp16(uint32_t dst, const float* src) {
    asm volatile("cp.async.cg.shared.global [%0], [%1], 16;"
                 :: "r"(dst), "l"(src) : "memory");
}
__device__ __forceinline__ void cp_commit() {
    asm volatile("cp.async.commit_group;" ::: "memory");
}
__device__ __forceinline__ void cp_wait2() {
    asm volatile("cp.async.wait_group 2;" ::: "memory");
}

__device__ __forceinline__ void mma_tf32(float* d, const unsigned int* a, const unsigned int* b) {
    asm volatile(
        "mma.sync.aligned.m16n8k8.row.col.f32.tf32.tf32.f32 "
        "{%0,%1,%2,%3},{%4,%5,%6,%7},{%8,%9},{%0,%1,%2,%3};"
        : "+f"(d[0]), "+f"(d[1]), "+f"(d[2]), "+f"(d[3])
        : "r"(a[0]), "r"(a[1]), "r"(a[2]), "r"(a[3]), "r"(b[0]), "r"(b[1]));
}

__global__ __launch_bounds__(256)
void gemm_tf32(const float* __restrict__ Ag, const float* __restrict__ Bg,
               float* __restrict__ Cg, int M, int N, int K) {
    extern __shared__ float sm[];

    const int tid  = threadIdx.x;
    const int lane = tid & 31;
    const int warp = tid >> 5;
    const int wm   = warp >> 2;         // 0..1
    const int wn   = warp & 3;          // 0..3
    const int brow = blockIdx.y * 128;
    const int bcol = blockIdx.x * 128;

    // cp.async load mappings (4 x 16B per thread for A, 4 for B)
    const int arow = tid >> 3;            // 0..31 (+32i)
    const int ac   = (tid & 7) * 4;       // 0..28
    const int br   = tid >> 5;            // 0..7 (+8i)
    const int bc   = (tid & 31) * 4;      // 0..124

    const float* Abase = Ag + (size_t)(brow + arow) * K + ac;
    const float* Bbase = Bg + (size_t)br * N + bcol + bc;

    const uint32_t smb = smem_u32(sm);
    const int nit = K >> 5;

    // issue one stage's copies (t = k-tile index); always commits a group
    auto issue = [&](int t) {
        if (t < nit) {
            const uint32_t sb = smb + (uint32_t)(t & (NSTAGE - 1)) * (STAGE_ELE * 4);
            const float* Ap = Abase + t * 32;
            const float* Bp = Bbase + (size_t)(t * 32) * N;
#pragma unroll
            for (int i = 0; i < 4; i++)
                cp16(sb + ((arow + 32 * i) * A_STRIDE + ac) * 4,
                     Ap + (size_t)(32 * i) * K);
            const uint32_t bsb = sb + 128 * A_STRIDE * 4;
#pragma unroll
            for (int i = 0; i < 4; i++)
                cp16(bsb + ((br + 8 * i) * B_STRIDE + bc) * 4,
                     Bp + (size_t)(8 * i) * N);
        }
        cp_commit();
    };

    const int lq = lane >> 2;           // 0..7
    const int lr = lane & 3;            // 0..3

    float acc[4][4][4];
#pragma unroll
    for (int mt = 0; mt < 4; mt++)
#pragma unroll
        for (int nt = 0; nt < 4; nt++)
#pragma unroll
            for (int e = 0; e < 4; e++) acc[mt][nt][e] = 0.f;

    // prologue: stages 0..2
    issue(0); issue(1); issue(2);

    for (int t = 0; t < nit; t++) {
        cp_wait2();          // stage t landed
        __syncthreads();     // all warps done with compute t-1 (buffer reuse safe)
        issue(t + 3);

        const float* Ab = sm + (size_t)(t & (NSTAGE - 1)) * STAGE_ELE;
        const float* Bb = Ab + 128 * A_STRIDE;

#pragma unroll
        for (int ks = 0; ks < 4; ks++) {
            const int k = ks * 8;
            unsigned int af[4][4], bf[4][2];
#pragma unroll
            for (int mt = 0; mt < 4; mt++) {
                const float* p = Ab + (size_t)(wm * 64 + mt * 16 + lq) * A_STRIDE + k + lr;
                af[mt][0] = __float_as_uint(p[0]);
                af[mt][1] = __float_as_uint(p[8 * A_STRIDE]);
                af[mt][2] = __float_as_uint(p[4]);
                af[mt][3] = __float_as_uint(p[8 * A_STRIDE + 4]);
            }
#pragma unroll
            for (int nt = 0; nt < 4; nt++) {
                const float* p = Bb + (size_t)(k + lr) * B_STRIDE + wn * 32 + nt * 8 + lq;
                bf[nt][0] = __float_as_uint(p[0]);
                bf[nt][1] = __float_as_uint(p[4 * B_STRIDE]);
            }
#pragma unroll
            for (int mt = 0; mt < 4; mt++)
#pragma unroll
                for (int nt = 0; nt < 4; nt++)
                    mma_tf32(acc[mt][nt], af[mt], bf[nt]);
        }
    }

    // epilogue
#pragma unroll
    for (int mt = 0; mt < 4; mt++) {
        const int r0 = brow + wm * 64 + mt * 16 + lq;
#pragma unroll
        for (int nt = 0; nt < 4; nt++) {
            const int c0 = bcol + wn * 32 + nt * 8 + lr * 2;
            *(float2*)&Cg[(size_t)r0 * N + c0]       = make_float2(acc[mt][nt][0], acc[mt][nt][1]);
            *(float2*)&Cg[(size_t)(r0 + 8) * N + c0] = make_float2(acc[mt][nt][2], acc[mt][nt][3]);
        }
    }
}

// ---------------------------------------------------------------------------
// tf32-RNA rounding pre-passes
// ---------------------------------------------------------------------------
__global__ void round_arr(const float* __restrict__ in, float* __restrict__ out, int n) {
    int idx = blockIdx.x * blockDim.x + threadIdx.x;
    int i4 = idx * 4;
    if (i4 + 3 < n) {
        float4 v = *(const float4*)(in + i4);
        v.x = f2tf32f(v.x); v.y = f2tf32f(v.y);
        v.z = f2tf32f(v.z); v.w = f2tf32f(v.w);
        *(float4*)(out + i4) = v;
    }
}

// ---------------------------------------------------------------------------
// Depthwise conv(3, pad 1) + bias + SiLU
// ---------------------------------------------------------------------------
__global__ void conv_silu(const float* __restrict__ conv_w,
                          const float* __restrict__ conv_b) {
    int idx = blockIdx.x * blockDim.x + threadIdx.x;
    if (idx >= NTOK * DI) return;
    int i  = idx & (DI - 1);
    int bt = idx >> 11;
    int t  = bt & (SEQ - 1);

    const float w0 = conv_w[i * 3 + 0];
    const float w1 = conv_w[i * 3 + 1];
    const float w2 = conv_w[i * 3 + 2];

    float xm1 = (t > 0)       ? g_XR[(size_t)(bt - 1) * (2 * DI) + i] : 0.f;
    float x0  =                 g_XR[(size_t)bt       * (2 * DI) + i];
    float xp1 = (t < SEQ - 1) ? g_XR[(size_t)(bt + 1) * (2 * DI) + i] : 0.f;

    float v = fmaf(w0, xm1, fmaf(w1, x0, fmaf(w2, xp1, conv_b[i])));
    v = v / (1.f + expf(-v));
    g_XC[idx] = v;
}

// ---------------------------------------------------------------------------
// B/C projections
// ---------------------------------------------------------------------------
__global__ __launch_bounds__(256)
void bc_gemm(const float* __restrict__ WB, const float* __restrict__ WC) {
    __shared__ float sh[32][33];
    const int row0 = blockIdx.x * 32;
    const int r = threadIdx.x & 31;
    const int g = threadIdx.x >> 5;
    const float* __restrict__ W = (g < 4) ? WB : WC;
    float* __restrict__ OUT = (g < 4) ? g_BT : g_CT;
    const int s0 = (g & 3) * 4;

    float acc[4] = {0.f, 0.f, 0.f, 0.f};
    const int lr  = threadIdx.x >> 3;
    const int lk4 = (threadIdx.x & 7) * 4;

    for (int k0 = 0; k0 < DI; k0 += 32) {
        float4 v = *(const float4*)&g_XC[(size_t)(row0 + lr) * DI + k0 + lk4];
        sh[lr][lk4 + 0] = v.x; sh[lr][lk4 + 1] = v.y;
        sh[lr][lk4 + 2] = v.z; sh[lr][lk4 + 3] = v.w;
        __syncthreads();
#pragma unroll 8
        for (int kk = 0; kk < 32; kk++) {
            float a = sh[r][kk];
            float4 w4 = *(const float4*)&W[(size_t)(k0 + kk) * DS + s0];
            acc[0] = fmaf(a, w4.x, acc[0]);
            acc[1] = fmaf(a, w4.y, acc[1]);
            acc[2] = fmaf(a, w4.z, acc[2]);
            acc[3] = fmaf(a, w4.w, acc[3]);
        }
        __syncthreads();
    }
#pragma unroll
    for (int j = 0; j < 4; j++)
        OUT[(size_t)(row0 + r) * DS + s0 + j] = acc[j];
}

// ---------------------------------------------------------------------------
// Scan (3-phase)
// ---------------------------------------------------------------------------
__global__ void scan_chunk(const float* __restrict__ A) {
    int idx = blockIdx.x * blockDim.x + threadIdx.x;
    if (idx >= BATCH * NCHUNK * DS) return;
    int s = idx & (DS - 1);
    int c = (idx >> 4) & (NCHUNK - 1);
    int b = idx >> 9;
    float d = 1.f / (1.f + expf(A[s]));
    float acc = 0.f;
    size_t base = ((size_t)b * SEQ + (size_t)c * CHUNK) * DS + s;
#pragma unroll 4
    for (int j = 0; j < CHUNK; j++)
        acc = fmaf(acc, d, g_BT[base + (size_t)j * DS]);
    g_S[idx] = acc;
}

__global__ void scan_carry(const float* __restrict__ A) {
    int idx = threadIdx.x;
    if (idx >= BATCH * DS) return;
    int s = idx & (DS - 1);
    int b = idx >> 4;
    float d = 1.f / (1.f + expf(A[s]));
    float dL = d;
#pragma unroll
    for (int q = 0; q < 7; q++) dL = dL * dL;
    float cur = 0.f;
    for (int c = 0; c < NCHUNK; c++) {
        int off = ((b * NCHUNK) + c) * DS + s;
        g_CAR[off] = cur;
        cur = fmaf(cur, dL, g_S[off]);
    }
}

__global__ void scan_ys(const float* __restrict__ A) {
    int bc = blockIdx.x;
    int b = bc >> 5, c = bc & 31;
    int lane = threadIdx.x;
    int s = lane & (DS - 1);
    float d = 1.f / (1.f + expf(A[s]));
    float state = (lane < DS) ? g_CAR[bc * DS + s] : 0.f;
    size_t base = ((size_t)b * SEQ + (size_t)c * CHUNK) * DS + s;
    int tout = b * SEQ + c * CHUNK;
    for (int j = 0; j < CHUNK; j++) {
        float v = 0.f;
        if (lane < DS) {
            size_t off = base + (size_t)j * DS;
            state = fmaf(state, d, g_BT[off]);
            v = state * g_CT[off];
        }
        v += __shfl_xor_sync(0xffffffffu, v, 8);
        v += __shfl_xor_sync(0xffffffffu, v, 4);
        v += __shfl_xor_sync(0xffffffffu, v, 2);
        v += __shfl_xor_sync(0xffffffffu, v, 1);
        if (lane == 0) g_YS[tout + j] = v;
    }
}

// ---------------------------------------------------------------------------
// Gate: Y = (ys + xc*D) * silu(res), tf32-rounded for GEMM2
// ---------------------------------------------------------------------------
__global__ void ygate(const float* __restrict__ Dp) {
    int idx = blockIdx.x * blockDim.x + threadIdx.x;
    if (idx >= NTOK * DI) return;
    int i  = idx & (DI - 1);
    int bt = idx >> 11;
    float res = g_XR[(size_t)bt * (2 * DI) + DI + i];
    float sres = res / (1.f + expf(-res));
    float v = fmaf(g_XC[idx], Dp[i], g_YS[bt]);
    g_Y[idx] = f2tf32f(v * sres);
}

// ---------------------------------------------------------------------------
extern "C" void kernel_launch(void* const* d_in, const int* in_sizes, int n_in,
                              void* d_out, int out_size) {
    const float* x      = (const float*)d_in[0];
    const float* W_in   = (const float*)d_in[1];
    const float* conv_w = (const float*)d_in[2];
    const float* conv_b = (const float*)d_in[3];
    const float* W_B    = (const float*)d_in[4];
    const float* W_C    = (const float*)d_in[5];
    const float* A      = (const float*)d_in[6];
    const float* D      = (const float*)d_in[7];
    const float* W_out  = (const float*)d_in[8];
    float* out = (float*)d_out;

    float* XR;  cudaGetSymbolAddress((void**)&XR,  g_XR);
    float* Y;   cudaGetSymbolAddress((void**)&Y,   g_Y);
    float* Xr;  cudaGetSymbolAddress((void**)&Xr,  g_Xr);
    float* W1;  cudaGetSymbolAddress((void**)&W1,  g_W1);
    float* W2;  cudaGetSymbolAddress((void**)&W2,  g_W2);

    static bool attr_set = false;
    if (!attr_set) {
        cudaFuncSetAttribute(gemm_tf32, cudaFuncAttributeMaxDynamicSharedMemorySize,
                             GEMM_SMEM_BYTES);
        attr_set = true;
    }

    // 0) tf32-round GEMM inputs
    round_arr<<<(NTOK * DM / 4) / 256, 256>>>(x, Xr, NTOK * DM);
    round_arr<<<(DM * 2 * DI / 4) / 256, 256>>>(W_in, W1, DM * 2 * DI);
    round_arr<<<(DI * DM / 4) / 256, 256>>>(W_out, W2, DI * DM);

    // 1) xr = x @ W_in   (16384 x 4096 x 1024)
    {
        dim3 grid((2 * DI) / 128, NTOK / 128);
        gemm_tf32<<<grid, 256, GEMM_SMEM_BYTES>>>(Xr, W1, XR, NTOK, 2 * DI, DM);
    }
    // 2) conv + silu
    conv_silu<<<(NTOK * DI) / 256, 256>>>(conv_w, conv_b);
    // 3) B/C projections
    bc_gemm<<<NTOK / 32, 256>>>(W_B, W_C);
    // 4) scan
    scan_chunk<<<(BATCH * NCHUNK * DS + 255) / 256, 256>>>(A);
    scan_carry<<<1, 64>>>(A);
    scan_ys<<<BATCH * NCHUNK, 32>>>(A);
    // 5) gate
    ygate<<<(NTOK * DI) / 256, 256>>>(D);
    // 6) out = Y @ W_out   (16384 x 1024 x 2048)
    {
        dim3 grid(DM / 128, NTOK / 128);
        gemm_tf32<<<grid, 256, GEMM_SMEM_BYTES>>>(Y, W2, out, NTOK, DM, DI);
    }
}

// round 8
// speedup vs baseline: 4.0194x; 1.0468x over previous
#include <cuda_runtime.h>
#include <cuda_bf16.h>
#include <cstdint>
#include <math.h>

// Problem constants
#define BATCH 4
#define SEQ   4096
#define DM    1024
#define DI    2048
#define DS    16
#define NTOK  (BATCH*SEQ)   // 16384
#define CHUNK 128
#define NCHUNK (SEQ/CHUNK)  // 32

// Scratch (device globals — no allocations allowed)
__device__ float g_XR[NTOK * 2 * DI];   // [x_main | res]
__device__ float g_XC[NTOK * DI];       // conv+silu output
__device__ float g_Y [NTOK * DI];       // gated pre-out (tf32-rounded)
__device__ float g_Xr[NTOK * DM];       // tf32-rounded x
__device__ float g_W1T[2 * DI * DM];    // W_in^T  [4096][1024] tf32-rounded
__device__ float g_W2T[DM * DI];        // W_out^T [1024][2048] tf32-rounded
__device__ float g_BT[NTOK * DS];
__device__ float g_CT[NTOK * DS];
__device__ float g_S [BATCH * NCHUNK * DS];
__device__ float g_CAR[BATCH * NCHUNK * DS];
__device__ float g_YS[NTOK];

__device__ __forceinline__ float f2tf32f(float x) {
    unsigned int r;
    asm("cvt.rna.tf32.f32 %0, %1;" : "=r"(r) : "f"(x));
    return __uint_as_float(r);
}

// ===========================================================================
// TF32 mma.sync GEMM, ldmatrix fragment loads, 4-stage cp.async pipeline.
// C(MxN) = A(MxK, row-major) * BT(NxK, row-major)^T.  Inputs pre-rounded tf32.
// CTA tile 128x128, BK=32, 256 threads (8 warps 2x4, warp tile 64x32).
// Both smem tiles: [128 rows][32 k], pad stride 36 floats.
// ===========================================================================
#define T_STRIDE 36
#define NSTAGE 4
#define STAGE_ELE (2 * 128 * T_STRIDE)               // 9216 floats
#define GEMM_SMEM_BYTES (NSTAGE * STAGE_ELE * 4)     // 147456 B

__device__ __forceinline__ uint32_t smem_u32(const void* p) {
    uint32_t a;
    asm("{ .reg .u64 t; cvta.to.shared.u64 t, %1; cvt.u32.u64 %0, t; }"
        : "=r"(a) : "l"(p));
    return a;
}
__device__ __forceinline__ void cp16(uint32_t dst, const float* src) {
    asm volatile("cp.async.cg.shared.global [%0], [%1], 16;"
                 :: "r"(dst), "l"(src) : "memory");
}
__device__ __forceinline__ void cp_commit() {
    asm volatile("cp.async.commit_group;" ::: "memory");
}
__device__ __forceinline__ void cp_wait2() {
    asm volatile("cp.async.wait_group 2;" ::: "memory");
}
__device__ __forceinline__ void ldsm4(unsigned int* r, uint32_t addr) {
    asm volatile("ldmatrix.sync.aligned.m8n8.x4.shared.b16 {%0,%1,%2,%3}, [%4];"
                 : "=r"(r[0]), "=r"(r[1]), "=r"(r[2]), "=r"(r[3]) : "r"(addr));
}
__device__ __forceinline__ void mma_tf32(float* d, const unsigned int* a, const unsigned int* b) {
    asm volatile(
        "mma.sync.aligned.m16n8k8.row.col.f32.tf32.tf32.f32 "
        "{%0,%1,%2,%3},{%4,%5,%6,%7},{%8,%9},{%0,%1,%2,%3};"
        : "+f"(d[0]), "+f"(d[1]), "+f"(d[2]), "+f"(d[3])
        : "r"(a[0]), "r"(a[1]), "r"(a[2]), "r"(a[3]), "r"(b[0]), "r"(b[1]));
}

__global__ __launch_bounds__(256)
void gemm_tf32(const float* __restrict__ Ag, const float* __restrict__ BTg,
               float* __restrict__ Cg, int M, int N, int K) {
    extern __shared__ float sm[];

    const int tid  = threadIdx.x;
    const int lane = tid & 31;
    const int warp = tid >> 5;
    const int wm   = warp >> 2;         // 0..1
    const int wn   = warp & 3;          // 0..3
    const int brow = blockIdx.y * 128;
    const int bcol = blockIdx.x * 128;

    // cp.async load mapping (both tiles identical: 128 rows x 32 k)
    const int lrow = tid >> 3;            // 0..31 (+32i)
    const int lc4  = (tid & 7) * 4;       // 0..28

    const float* Abase = Ag  + (size_t)(brow + lrow) * K + lc4;
    const float* Bbase = BTg + (size_t)(bcol + lrow) * K + lc4;

    const uint32_t smb = smem_u32(sm);
    const int nit = K >> 5;

    auto issue = [&](int t) {
        if (t < nit) {
            const uint32_t sb = smb + (uint32_t)(t & (NSTAGE - 1)) * (STAGE_ELE * 4);
            const float* Ap = Abase + t * 32;
            const float* Bp = Bbase + t * 32;
#pragma unroll
            for (int i = 0; i < 4; i++)
                cp16(sb + ((lrow + 32 * i) * T_STRIDE + lc4) * 4,
                     Ap + (size_t)(32 * i) * K);
            const uint32_t bsb = sb + 128 * T_STRIDE * 4;
#pragma unroll
            for (int i = 0; i < 4; i++)
                cp16(bsb + ((lrow + 32 * i) * T_STRIDE + lc4) * 4,
                     Bp + (size_t)(32 * i) * K);
        }
        cp_commit();
    };

    // ldmatrix per-lane address components
    const int a_row = wm * 64 + ((lane >> 3) & 1) * 8 + (lane & 7); // + mt*16
    const int a_col = (lane >> 4) * 4;                              // 0 or 4
    const int b_row = wn * 32 + ((lane >> 4) & 1) * 8 + (lane & 7); // + nt2*16
    const int b_col = ((lane >> 3) & 1) * 4;                        // 0 or 4

    const int lq = lane >> 2;           // 0..7
    const int lr = lane & 3;            // 0..3

    float acc[4][4][4];
#pragma unroll
    for (int mt = 0; mt < 4; mt++)
#pragma unroll
        for (int nt = 0; nt < 4; nt++)
#pragma unroll
            for (int e = 0; e < 4; e++) acc[mt][nt][e] = 0.f;

    issue(0); issue(1); issue(2);

    for (int t = 0; t < nit; t++) {
        cp_wait2();
        __syncthreads();
        issue(t + 3);

        const uint32_t ab = smb + (uint32_t)(t & (NSTAGE - 1)) * (STAGE_ELE * 4);
        const uint32_t bb = ab + 128 * T_STRIDE * 4;

#pragma unroll
        for (int ks = 0; ks < 4; ks++) {
            const int k = ks * 8;
            unsigned int af[4][4], bf[2][4];
#pragma unroll
            for (int mt = 0; mt < 4; mt++)
                ldsm4(af[mt], ab + ((a_row + mt * 16) * T_STRIDE + k + a_col) * 4);
#pragma unroll
            for (int nt2 = 0; nt2 < 2; nt2++)
                ldsm4(bf[nt2], bb + ((b_row + nt2 * 16) * T_STRIDE + k + b_col) * 4);
#pragma unroll
            for (int mt = 0; mt < 4; mt++)
#pragma unroll
                for (int nt = 0; nt < 4; nt++)
                    mma_tf32(acc[mt][nt], af[mt], &bf[nt >> 1][(nt & 1) * 2]);
        }
    }

    // epilogue
#pragma unroll
    for (int mt = 0; mt < 4; mt++) {
        const int r0 = brow + wm * 64 + mt * 16 + lq;
#pragma unroll
        for (int nt = 0; nt < 4; nt++) {
            const int c0 = bcol + wn * 32 + nt * 8 + lr * 2;
            *(float2*)&Cg[(size_t)r0 * N + c0]       = make_float2(acc[mt][nt][0], acc[mt][nt][1]);
            *(float2*)&Cg[(size_t)(r0 + 8) * N + c0] = make_float2(acc[mt][nt][2], acc[mt][nt][3]);
        }
    }
}

// ---------------------------------------------------------------------------
// Pre-passes
// ---------------------------------------------------------------------------
__global__ void round_arr(const float* __restrict__ in, float* __restrict__ out, int n) {
    int idx = blockIdx.x * blockDim.x + threadIdx.x;
    int i4 = idx * 4;
    if (i4 + 3 < n) {
        float4 v = *(const float4*)(in + i4);
        v.x = f2tf32f(v.x); v.y = f2tf32f(v.y);
        v.z = f2tf32f(v.z); v.w = f2tf32f(v.w);
        *(float4*)(out + i4) = v;
    }
}

// out[n][m] = round(in[m][n]); in is R x Cc, out is Cc x R
__global__ void transpose_round(const float* __restrict__ in, float* __restrict__ out,
                                int R, int Cc) {
    __shared__ float t[32][33];
    int bx = blockIdx.x * 32, by = blockIdx.y * 32;
#pragma unroll
    for (int j = 0; j < 32; j += 8) {
        int y = by + threadIdx.y + j, x = bx + threadIdx.x;
        t[threadIdx.y + j][threadIdx.x] = in[(size_t)y * Cc + x];
    }
    __syncthreads();
#pragma unroll
    for (int j = 0; j < 32; j += 8) {
        int y = bx + threadIdx.y + j, x = by + threadIdx.x;
        out[(size_t)y * R + x] = f2tf32f(t[threadIdx.x][threadIdx.y + j]);
    }
}

// ---------------------------------------------------------------------------
// Depthwise conv(3, pad 1) + bias + SiLU
// ---------------------------------------------------------------------------
__global__ void conv_silu(const float* __restrict__ conv_w,
                          const float* __restrict__ conv_b) {
    int idx = blockIdx.x * blockDim.x + threadIdx.x;
    if (idx >= NTOK * DI) return;
    int i  = idx & (DI - 1);
    int bt = idx >> 11;
    int t  = bt & (SEQ - 1);

    const float w0 = conv_w[i * 3 + 0];
    const float w1 = conv_w[i * 3 + 1];
    const float w2 = conv_w[i * 3 + 2];

    float xm1 = (t > 0)       ? g_XR[(size_t)(bt - 1) * (2 * DI) + i] : 0.f;
    float x0  =                 g_XR[(size_t)bt       * (2 * DI) + i];
    float xp1 = (t < SEQ - 1) ? g_XR[(size_t)(bt + 1) * (2 * DI) + i] : 0.f;

    float v = fmaf(w0, xm1, fmaf(w1, x0, fmaf(w2, xp1, conv_b[i])));
    v = v / (1.f + expf(-v));
    g_XC[idx] = v;
}

// ---------------------------------------------------------------------------
// B/C projections
// ---------------------------------------------------------------------------
__global__ __launch_bounds__(256)
void bc_gemm(const float* __restrict__ WB, const float* __restrict__ WC) {
    __shared__ float sh[32][33];
    const int row0 = blockIdx.x * 32;
    const int r = threadIdx.x & 31;
    const int g = threadIdx.x >> 5;
    const float* __restrict__ W = (g < 4) ? WB : WC;
    float* __restrict__ OUT = (g < 4) ? g_BT : g_CT;
    const int s0 = (g & 3) * 4;

    float acc[4] = {0.f, 0.f, 0.f, 0.f};
    const int lr  = threadIdx.x >> 3;
    const int lk4 = (threadIdx.x & 7) * 4;

    for (int k0 = 0; k0 < DI; k0 += 32) {
        float4 v = *(const float4*)&g_XC[(size_t)(row0 + lr) * DI + k0 + lk4];
        sh[lr][lk4 + 0] = v.x; sh[lr][lk4 + 1] = v.y;
        sh[lr][lk4 + 2] = v.z; sh[lr][lk4 + 3] = v.w;
        __syncthreads();
#pragma unroll 8
        for (int kk = 0; kk < 32; kk++) {
            float a = sh[r][kk];
            float4 w4 = *(const float4*)&W[(size_t)(k0 + kk) * DS + s0];
            acc[0] = fmaf(a, w4.x, acc[0]);
            acc[1] = fmaf(a, w4.y, acc[1]);
            acc[2] = fmaf(a, w4.z, acc[2]);
            acc[3] = fmaf(a, w4.w, acc[3]);
        }
        __syncthreads();
    }
#pragma unroll
    for (int j = 0; j < 4; j++)
        OUT[(size_t)(row0 + r) * DS + s0 + j] = acc[j];
}

// ---------------------------------------------------------------------------
// Scan (3-phase)
// ---------------------------------------------------------------------------
__global__ void scan_chunk(const float* __restrict__ A) {
    int idx = blockIdx.x * blockDim.x + threadIdx.x;
    if (idx >= BATCH * NCHUNK * DS) return;
    int s = idx & (DS - 1);
    int c = (idx >> 4) & (NCHUNK - 1);
    int b = idx >> 9;
    float d = 1.f / (1.f + expf(A[s]));
    float acc = 0.f;
    size_t base = ((size_t)b * SEQ + (size_t)c * CHUNK) * DS + s;
#pragma unroll 4
    for (int j = 0; j < CHUNK; j++)
        acc = fmaf(acc, d, g_BT[base + (size_t)j * DS]);
    g_S[idx] = acc;
}

__global__ void scan_carry(const float* __restrict__ A) {
    int idx = threadIdx.x;
    if (idx >= BATCH * DS) return;
    int s = idx & (DS - 1);
    int b = idx >> 4;
    float d = 1.f / (1.f + expf(A[s]));
    float dL = d;
#pragma unroll
    for (int q = 0; q < 7; q++) dL = dL * dL;
    float cur = 0.f;
    for (int c = 0; c < NCHUNK; c++) {
        int off = ((b * NCHUNK) + c) * DS + s;
        g_CAR[off] = cur;
        cur = fmaf(cur, dL, g_S[off]);
    }
}

__global__ void scan_ys(const float* __restrict__ A) {
    int bc = blockIdx.x;
    int b = bc >> 5, c = bc & 31;
    int lane = threadIdx.x;
    int s = lane & (DS - 1);
    float d = 1.f / (1.f + expf(A[s]));
    float state = (lane < DS) ? g_CAR[bc * DS + s] : 0.f;
    size_t base = ((size_t)b * SEQ + (size_t)c * CHUNK) * DS + s;
    int tout = b * SEQ + c * CHUNK;
    for (int j = 0; j < CHUNK; j++) {
        float v = 0.f;
        if (lane < DS) {
            size_t off = base + (size_t)j * DS;
            state = fmaf(state, d, g_BT[off]);
            v = state * g_CT[off];
        }
        v += __shfl_xor_sync(0xffffffffu, v, 8);
        v += __shfl_xor_sync(0xffffffffu, v, 4);
        v += __shfl_xor_sync(0xffffffffu, v, 2);
        v += __shfl_xor_sync(0xffffffffu, v, 1);
        if (lane == 0) g_YS[tout + j] = v;
    }
}

// ---------------------------------------------------------------------------
// Gate: Y = (ys + xc*D) * silu(res), tf32-rounded for GEMM2
// ---------------------------------------------------------------------------
__global__ void ygate(const float* __restrict__ Dp) {
    int idx = blockIdx.x * blockDim.x + threadIdx.x;
    if (idx >= NTOK * DI) return;
    int i  = idx & (DI - 1);
    int bt = idx >> 11;
    float res = g_XR[(size_t)bt * (2 * DI) + DI + i];
    float sres = res / (1.f + expf(-res));
    float v = fmaf(g_XC[idx], Dp[i], g_YS[bt]);
    g_Y[idx] = f2tf32f(v * sres);
}

// ---------------------------------------------------------------------------
extern "C" void kernel_launch(void* const* d_in, const int* in_sizes, int n_in,
                              void* d_out, int out_size) {
    const float* x      = (const float*)d_in[0];
    const float* W_in   = (const float*)d_in[1];
    const float* conv_w = (const float*)d_in[2];
    const float* conv_b = (const float*)d_in[3];
    const float* W_B    = (const float*)d_in[4];
    const float* W_C    = (const float*)d_in[5];
    const float* A      = (const float*)d_in[6];
    const float* D      = (const float*)d_in[7];
    const float* W_out  = (const float*)d_in[8];
    float* out = (float*)d_out;

    float* XR;   cudaGetSymbolAddress((void**)&XR,   g_XR);
    float* Y;    cudaGetSymbolAddress((void**)&Y,    g_Y);
    float* Xr;   cudaGetSymbolAddress((void**)&Xr,   g_Xr);
    float* W1T;  cudaGetSymbolAddress((void**)&W1T,  g_W1T);
    float* W2T;  cudaGetSymbolAddress((void**)&W2T,  g_W2T);

    static bool attr_set = false;
    if (!attr_set) {
        cudaFuncSetAttribute(gemm_tf32, cudaFuncAttributeMaxDynamicSharedMemorySize,
                             GEMM_SMEM_BYTES);
        attr_set = true;
    }

    // 0) round x; transpose+round weights
    round_arr<<<(NTOK * DM / 4) / 256, 256>>>(x, Xr, NTOK * DM);
    {
        dim3 g((2 * DI) / 32, DM / 32);
        transpose_round<<<g, dim3(32, 8)>>>(W_in, W1T, DM, 2 * DI);
    }
    {
        dim3 g(DM / 32, DI / 32);
        transpose_round<<<g, dim3(32, 8)>>>(W_out, W2T, DI, DM);
    }

    // 1) xr = x @ W_in   (16384 x 4096 x 1024)
    {
        dim3 grid((2 * DI) / 128, NTOK / 128);
        gemm_tf32<<<grid, 256, GEMM_SMEM_BYTES>>>(Xr, W1T, XR, NTOK, 2 * DI, DM);
    }
    // 2) conv + silu
    conv_silu<<<(NTOK * DI) / 256, 256>>>(conv_w, conv_b);
    // 3) B/C projections
    bc_gemm<<<NTOK / 32, 256>>>(W_B, W_C);
    // 4) scan
    scan_chunk<<<(BATCH * NCHUNK * DS + 255) / 256, 256>>>(A);
    scan_carry<<<1, 64>>>(A);
    scan_ys<<<BATCH * NCHUNK, 32>>>(A);
    // 5) gate
    ygate<<<(NTOK * DI) / 256, 256>>>(D);
    // 6) out = Y @ W_out   (16384 x 1024 x 2048)
    {
        dim3 grid(DM / 128, NTOK / 128);
        gemm_tf32<<<grid, 256, GEMM_SMEM_BYTES>>>(Y, W2T, out, NTOK, DM, DI);
    }
}

// round 10
// speedup vs baseline: 4.4907x; 1.1172x over previous
#include <cuda_runtime.h>
#include <cuda_bf16.h>
#include <cstdint>
#include <math.h>

// Problem constants
#define BATCH 4
#define SEQ   4096
#define DM    1024
#define DI    2048
#define DS    16
#define NTOK  (BATCH*SEQ)   // 16384
#define CHUNK 128
#define NCHUNK (SEQ/CHUNK)  // 32

// Scratch (device globals — no allocations allowed)
__device__ float g_XR[NTOK * 2 * DI];   // [x_main | res]
__device__ float g_XC[NTOK * DI];       // conv+silu output
__device__ float g_Y [NTOK * DI];       // gated pre-out (tf32-rounded)
__device__ float g_Xr[NTOK * DM];       // tf32-rounded x
__device__ float g_W1T[2 * DI * DM];    // W_in^T  [4096][1024] tf32-rounded
__device__ float g_W2T[DM * DI];        // W_out^T [1024][2048] tf32-rounded
__device__ float g_BT[NTOK * DS];
__device__ float g_CT[NTOK * DS];
__device__ float g_S [BATCH * NCHUNK * DS];
__device__ float g_CAR[BATCH * NCHUNK * DS];
__device__ float g_YS[NTOK];

__device__ __forceinline__ float f2tf32f(float x) {
    unsigned int r;
    asm("cvt.rna.tf32.f32 %0, %1;" : "=r"(r) : "f"(x));
    return __uint_as_float(r);
}

// ===========================================================================
// TF32 mma.sync GEMM, ldmatrix fragment loads (register double-buffered),
// 3-stage cp.async pipeline (110.6 KB smem -> 2 CTAs/SM).
// C(MxN) = A(MxK, row-major) * BT(NxK, row-major)^T.  Inputs pre-rounded tf32.
// CTA tile 128x128, BK=32, 256 threads (8 warps 2x4, warp tile 64x32).
// Both smem tiles: [128 rows][32 k], pad stride 36 floats.
// ===========================================================================
#define T_STRIDE 36
#define NSTAGE 3
#define STAGE_ELE (2 * 128 * T_STRIDE)               // 9216 floats = 36864 B
#define GEMM_SMEM_BYTES (NSTAGE * STAGE_ELE * 4)     // 110592 B

__device__ __forceinline__ uint32_t smem_u32(const void* p) {
    uint32_t a;
    asm("{ .reg .u64 t; cvta.to.shared.u64 t, %1; cvt.u32.u64 %0, t; }"
        : "=r"(a) : "l"(p));
    return a;
}
__device__ __forceinline__ void cp16(uint32_t dst, const float* src) {
    asm volatile("cp.async.cg.shared.global [%0], [%1], 16;"
                 :: "r"(dst), "l"(src) : "memory");
}
__device__ __forceinline__ void cp_commit() {
    asm volatile("cp.async.commit_group;" ::: "memory");
}
__device__ __forceinline__ void cp_wait1() {
    asm volatile("cp.async.wait_group 1;" ::: "memory");
}
__device__ __forceinline__ void ldsm4(unsigned int* r, uint32_t addr) {
    asm volatile("ldmatrix.sync.aligned.m8n8.x4.shared.b16 {%0,%1,%2,%3}, [%4];"
                 : "=r"(r[0]), "=r"(r[1]), "=r"(r[2]), "=r"(r[3]) : "r"(addr));
}
__device__ __forceinline__ void mma_tf32(float* d, const unsigned int* a, const unsigned int* b) {
    asm volatile(
        "mma.sync.aligned.m16n8k8.row.col.f32.tf32.tf32.f32 "
        "{%0,%1,%2,%3},{%4,%5,%6,%7},{%8,%9},{%0,%1,%2,%3};"
        : "+f"(d[0]), "+f"(d[1]), "+f"(d[2]), "+f"(d[3])
        : "r"(a[0]), "r"(a[1]), "r"(a[2]), "r"(a[3]), "r"(b[0]), "r"(b[1]));
}

__global__ __launch_bounds__(256, 2)
void gemm_tf32(const float* __restrict__ Ag, const float* __restrict__ BTg,
               float* __restrict__ Cg, int M, int N, int K) {
    extern __shared__ float sm[];

    const int tid  = threadIdx.x;
    const int lane = tid & 31;
    const int warp = tid >> 5;
    const int wm   = warp >> 2;         // 0..1
    const int wn   = warp & 3;          // 0..3
    const int brow = blockIdx.y * 128;
    const int bcol = blockIdx.x * 128;

    // cp.async load mapping (both tiles identical: 128 rows x 32 k)
    const int lrow = tid >> 3;            // 0..31 (+32i)
    const int lc4  = (tid & 7) * 4;       // 0..28

    const float* Abase = Ag  + (size_t)(brow + lrow) * K + lc4;
    const float* Bbase = BTg + (size_t)(bcol + lrow) * K + lc4;

    const uint32_t smb = smem_u32(sm);
    const int nit = K >> 5;

    auto issue = [&](int t) {
        if (t < nit) {
            int st = t % NSTAGE;
            const uint32_t sb = smb + (uint32_t)st * (STAGE_ELE * 4);
            const float* Ap = Abase + t * 32;
            const float* Bp = Bbase + t * 32;
#pragma unroll
            for (int i = 0; i < 4; i++)
                cp16(sb + ((lrow + 32 * i) * T_STRIDE + lc4) * 4,
                     Ap + (size_t)(32 * i) * K);
            const uint32_t bsb = sb + 128 * T_STRIDE * 4;
#pragma unroll
            for (int i = 0; i < 4; i++)
                cp16(bsb + ((lrow + 32 * i) * T_STRIDE + lc4) * 4,
                     Bp + (size_t)(32 * i) * K);
        }
        cp_commit();
    };

    // ldmatrix per-lane address components
    const int a_row = wm * 64 + ((lane >> 3) & 1) * 8 + (lane & 7); // + mt*16
    const int a_col = (lane >> 4) * 4;                              // 0 or 4
    const int b_row = wn * 32 + ((lane >> 4) & 1) * 8 + (lane & 7); // + nt2*16
    const int b_col = ((lane >> 3) & 1) * 4;                        // 0 or 4

    const int lq = lane >> 2;           // 0..7
    const int lr = lane & 3;            // 0..3

    float acc[4][4][4];
#pragma unroll
    for (int mt = 0; mt < 4; mt++)
#pragma unroll
        for (int nt = 0; nt < 4; nt++)
#pragma unroll
            for (int e = 0; e < 4; e++) acc[mt][nt][e] = 0.f;

    issue(0); issue(1);

    unsigned int af[2][4][4], bf[2][2][4];

    for (int t = 0; t < nit; t++) {
        cp_wait1();          // stage t landed
        __syncthreads();     // buffer (t+2)%3 free (compute t-1 done everywhere)
        issue(t + 2);

        const uint32_t ab = smb + (uint32_t)(t % NSTAGE) * (STAGE_ELE * 4);
        const uint32_t bb = ab + 128 * T_STRIDE * 4;

        // preload k-step 0 fragments
#pragma unroll
        for (int mt = 0; mt < 4; mt++)
            ldsm4(af[0][mt], ab + ((a_row + mt * 16) * T_STRIDE + 0 + a_col) * 4);
#pragma unroll
        for (int nt2 = 0; nt2 < 2; nt2++)
            ldsm4(bf[0][nt2], bb + ((b_row + nt2 * 16) * T_STRIDE + 0 + b_col) * 4);

#pragma unroll
        for (int ks = 0; ks < 4; ks++) {
            const int cur = ks & 1;
            if (ks < 3) {
                const int k = (ks + 1) * 8;
                const int nxt = cur ^ 1;
#pragma unroll
                for (int mt = 0; mt < 4; mt++)
                    ldsm4(af[nxt][mt], ab + ((a_row + mt * 16) * T_STRIDE + k + a_col) * 4);
#pragma unroll
                for (int nt2 = 0; nt2 < 2; nt2++)
                    ldsm4(bf[nxt][nt2], bb + ((b_row + nt2 * 16) * T_STRIDE + k + b_col) * 4);
            }
#pragma unroll
            for (int mt = 0; mt < 4; mt++)
#pragma unroll
                for (int nt = 0; nt < 4; nt++)
                    mma_tf32(acc[mt][nt], af[cur][mt], &bf[cur][nt >> 1][(nt & 1) * 2]);
        }
    }

    // epilogue
#pragma unroll
    for (int mt = 0; mt < 4; mt++) {
        const int r0 = brow + wm * 64 + mt * 16 + lq;
#pragma unroll
        for (int nt = 0; nt < 4; nt++) {
            const int c0 = bcol + wn * 32 + nt * 8 + lr * 2;
            *(float2*)&Cg[(size_t)r0 * N + c0]       = make_float2(acc[mt][nt][0], acc[mt][nt][1]);
            *(float2*)&Cg[(size_t)(r0 + 8) * N + c0] = make_float2(acc[mt][nt][2], acc[mt][nt][3]);
        }
    }
}

// ---------------------------------------------------------------------------
// Pre-passes
// ---------------------------------------------------------------------------
__global__ void round_arr(const float* __restrict__ in, float* __restrict__ out, int n) {
    int idx = blockIdx.x * blockDim.x + threadIdx.x;
    int i4 = idx * 4;
    if (i4 + 3 < n) {
        float4 v = *(const float4*)(in + i4);
        v.x = f2tf32f(v.x); v.y = f2tf32f(v.y);
        v.z = f2tf32f(v.z); v.w = f2tf32f(v.w);
        *(float4*)(out + i4) = v;
    }
}

// out[n][m] = round(in[m][n]); in is R x Cc, out is Cc x R
__global__ void transpose_round(const float* __restrict__ in, float* __restrict__ out,
                                int R, int Cc) {
    __shared__ float t[32][33];
    int bx = blockIdx.x * 32, by = blockIdx.y * 32;
#pragma unroll
    for (int j = 0; j < 32; j += 8) {
        int y = by + threadIdx.y + j, x = bx + threadIdx.x;
        t[threadIdx.y + j][threadIdx.x] = in[(size_t)y * Cc + x];
    }
    __syncthreads();
#pragma unroll
    for (int j = 0; j < 32; j += 8) {
        int y = bx + threadIdx.y + j, x = by + threadIdx.x;
        out[(size_t)y * R + x] = f2tf32f(t[threadIdx.x][threadIdx.y + j]);
    }
}

// ---------------------------------------------------------------------------
// Depthwise conv(3, pad 1) + bias + SiLU
// ---------------------------------------------------------------------------
__global__ void conv_silu(const float* __restrict__ conv_w,
                          const float* __restrict__ conv_b) {
    int idx = blockIdx.x * blockDim.x + threadIdx.x;
    if (idx >= NTOK * DI) return;
    int i  = idx & (DI - 1);
    int bt = idx >> 11;
    int t  = bt & (SEQ - 1);

    const float w0 = conv_w[i * 3 + 0];
    const float w1 = conv_w[i * 3 + 1];
    const float w2 = conv_w[i * 3 + 2];

    float xm1 = (t > 0)       ? g_XR[(size_t)(bt - 1) * (2 * DI) + i] : 0.f;
    float x0  =                 g_XR[(size_t)bt       * (2 * DI) + i];
    float xp1 = (t < SEQ - 1) ? g_XR[(size_t)(bt + 1) * (2 * DI) + i] : 0.f;

    float v = fmaf(w0, xm1, fmaf(w1, x0, fmaf(w2, xp1, conv_b[i])));
    v = v / (1.f + expf(-v));
    g_XC[idx] = v;
}

// ---------------------------------------------------------------------------
// B/C projections
// ---------------------------------------------------------------------------
__global__ __launch_bounds__(256)
void bc_gemm(const float* __restrict__ WB, const float* __restrict__ WC) {
    __shared__ float sh[32][33];
    const int row0 = blockIdx.x * 32;
    const int r = threadIdx.x & 31;
    const int g = threadIdx.x >> 5;
    const float* __restrict__ W = (g < 4) ? WB : WC;
    float* __restrict__ OUT = (g < 4) ? g_BT : g_CT;
    const int s0 = (g & 3) * 4;

    float acc[4] = {0.f, 0.f, 0.f, 0.f};
    const int lr  = threadIdx.x >> 3;
    const int lk4 = (threadIdx.x & 7) * 4;

    for (int k0 = 0; k0 < DI; k0 += 32) {
        float4 v = *(const float4*)&g_XC[(size_t)(row0 + lr) * DI + k0 + lk4];
        sh[lr][lk4 + 0] = v.x; sh[lr][lk4 + 1] = v.y;
        sh[lr][lk4 + 2] = v.z; sh[lr][lk4 + 3] = v.w;
        __syncthreads();
#pragma unroll 8
        for (int kk = 0; kk < 32; kk++) {
            float a = sh[r][kk];
            float4 w4 = *(const float4*)&W[(size_t)(k0 + kk) * DS + s0];
            acc[0] = fmaf(a, w4.x, acc[0]);
            acc[1] = fmaf(a, w4.y, acc[1]);
            acc[2] = fmaf(a, w4.z, acc[2]);
            acc[3] = fmaf(a, w4.w, acc[3]);
        }
        __syncthreads();
    }
#pragma unroll
    for (int j = 0; j < 4; j++)
        OUT[(size_t)(row0 + r) * DS + s0 + j] = acc[j];
}

// ---------------------------------------------------------------------------
// Scan (3-phase)
// ---------------------------------------------------------------------------
__global__ void scan_chunk(const float* __restrict__ A) {
    int idx = blockIdx.x * blockDim.x + threadIdx.x;
    if (idx >= BATCH * NCHUNK * DS) return;
    int s = idx & (DS - 1);
    int c = (idx >> 4) & (NCHUNK - 1);
    int b = idx >> 9;
    float d = 1.f / (1.f + expf(A[s]));
    float acc = 0.f;
    size_t base = ((size_t)b * SEQ + (size_t)c * CHUNK) * DS + s;
#pragma unroll 4
    for (int j = 0; j < CHUNK; j++)
        acc = fmaf(acc, d, g_BT[base + (size_t)j * DS]);
    g_S[idx] = acc;
}

__global__ void scan_carry(const float* __restrict__ A) {
    int idx = threadIdx.x;
    if (idx >= BATCH * DS) return;
    int s = idx & (DS - 1);
    int b = idx >> 4;
    float d = 1.f / (1.f + expf(A[s]));
    float dL = d;
#pragma unroll
    for (int q = 0; q < 7; q++) dL = dL * dL;
    float cur = 0.f;
    for (int c = 0; c < NCHUNK; c++) {
        int off = ((b * NCHUNK) + c) * DS + s;
        g_CAR[off] = cur;
        cur = fmaf(cur, dL, g_S[off]);
    }
}

__global__ void scan_ys(const float* __restrict__ A) {
    int bc = blockIdx.x;
    int b = bc >> 5, c = bc & 31;
    int lane = threadIdx.x;
    int s = lane & (DS - 1);
    float d = 1.f / (1.f + expf(A[s]));
    float state = (lane < DS) ? g_CAR[bc * DS + s] : 0.f;
    size_t base = ((size_t)b * SEQ + (size_t)c * CHUNK) * DS + s;
    int tout = b * SEQ + c * CHUNK;
    for (int j = 0; j < CHUNK; j++) {
        float v = 0.f;
        if (lane < DS) {
            size_t off = base + (size_t)j * DS;
            state = fmaf(state, d, g_BT[off]);
            v = state * g_CT[off];
        }
        v += __shfl_xor_sync(0xffffffffu, v, 8);
        v += __shfl_xor_sync(0xffffffffu, v, 4);
        v += __shfl_xor_sync(0xffffffffu, v, 2);
        v += __shfl_xor_sync(0xffffffffu, v, 1);
        if (lane == 0) g_YS[tout + j] = v;
    }
}

// ---------------------------------------------------------------------------
// Gate: Y = (ys + xc*D) * silu(res), tf32-rounded for GEMM2
// ---------------------------------------------------------------------------
__global__ void ygate(const float* __restrict__ Dp) {
    int idx = blockIdx.x * blockDim.x + threadIdx.x;
    if (idx >= NTOK * DI) return;
    int i  = idx & (DI - 1);
    int bt = idx >> 11;
    float res = g_XR[(size_t)bt * (2 * DI) + DI + i];
    float sres = res / (1.f + expf(-res));
    float v = fmaf(g_XC[idx], Dp[i], g_YS[bt]);
    g_Y[idx] = f2tf32f(v * sres);
}

// ---------------------------------------------------------------------------
extern "C" void kernel_launch(void* const* d_in, const int* in_sizes, int n_in,
                              void* d_out, int out_size) {
    const float* x      = (const float*)d_in[0];
    const float* W_in   = (const float*)d_in[1];
    const float* conv_w = (const float*)d_in[2];
    const float* conv_b = (const float*)d_in[3];
    const float* W_B    = (const float*)d_in[4];
    const float* W_C    = (const float*)d_in[5];
    const float* A      = (const float*)d_in[6];
    const float* D      = (const float*)d_in[7];
    const float* W_out  = (const float*)d_in[8];
    float* out = (float*)d_out;

    float* XR;   cudaGetSymbolAddress((void**)&XR,   g_XR);
    float* Y;    cudaGetSymbolAddress((void**)&Y,    g_Y);
    float* Xr;   cudaGetSymbolAddress((void**)&Xr,   g_Xr);
    float* W1T;  cudaGetSymbolAddress((void**)&W1T,  g_W1T);
    float* W2T;  cudaGetSymbolAddress((void**)&W2T,  g_W2T);

    static bool attr_set = false;
    if (!attr_set) {
        cudaFuncSetAttribute(gemm_tf32, cudaFuncAttributeMaxDynamicSharedMemorySize,
                             GEMM_SMEM_BYTES);
        attr_set = true;
    }

    // 0) round x; transpose+round weights
    round_arr<<<(NTOK * DM / 4) / 256, 256>>>(x, Xr, NTOK * DM);
    {
        dim3 g((2 * DI) / 32, DM / 32);
        transpose_round<<<g, dim3(32, 8)>>>(W_in, W1T, DM, 2 * DI);
    }
    {
        dim3 g(DM / 32, DI / 32);
        transpose_round<<<g, dim3(32, 8)>>>(W_out, W2T, DI, DM);
    }

    // 1) xr = x @ W_in   (16384 x 4096 x 1024)
    {
        dim3 grid((2 * DI) / 128, NTOK / 128);
        gemm_tf32<<<grid, 256, GEMM_SMEM_BYTES>>>(Xr, W1T, XR, NTOK, 2 * DI, DM);
    }
    // 2) conv + silu
    conv_silu<<<(NTOK * DI) / 256, 256>>>(conv_w, conv_b);
    // 3) B/C projections
    bc_gemm<<<NTOK / 32, 256>>>(W_B, W_C);
    // 4) scan
    scan_chunk<<<(BATCH * NCHUNK * DS + 255) / 256, 256>>>(A);
    scan_carry<<<1, 64>>>(A);
    scan_ys<<<BATCH * NCHUNK, 32>>>(A);
    // 5) gate
    ygate<<<(NTOK * DI) / 256, 256>>>(D);
    // 6) out = Y @ W_out   (16384 x 1024 x 2048)
    {
        dim3 grid(DM / 128, NTOK / 128);
        gemm_tf32<<<grid, 256, GEMM_SMEM_BYTES>>>(Y, W2T, out, NTOK, DM, DI);
    }
}

// round 15
// speedup vs baseline: 4.8735x; 1.0852x over previous
#include <cuda_runtime.h>
#include <cuda_bf16.h>
#include <cstdint>
#include <math.h>

// Problem constants
#define BATCH 4
#define SEQ   4096
#define DM    1024
#define DI    2048
#define DS    16
#define NTOK  (BATCH*SEQ)   // 16384
#define CHUNK 128
#define NCHUNK (SEQ/CHUNK)  // 32

// Scratch (device globals — no allocations allowed)
__device__ float g_XR[NTOK * 2 * DI];   // [x_main | res]
__device__ float g_XC[NTOK * DI];       // conv+silu output
__device__ float g_Y [NTOK * DI];       // gated pre-out (tf32-rounded)
__device__ float g_Xr[NTOK * DM];       // tf32-rounded x
__device__ float g_W1T[2 * DI * DM];    // W_in^T  [4096][1024] tf32-rounded
__device__ float g_W2T[DM * DI];        // W_out^T [1024][2048] tf32-rounded
__device__ float g_BT[NTOK * DS];
__device__ float g_CT[NTOK * DS];
__device__ float g_S [BATCH * NCHUNK * DS];
__device__ float g_CAR[BATCH * NCHUNK * DS];
__device__ float g_YS[NTOK];

__device__ __forceinline__ float f2tf32f(float x) {
    unsigned int r;
    asm("cvt.rna.tf32.f32 %0, %1;" : "=r"(r) : "f"(x));
    return __uint_as_float(r);
}
__device__ __forceinline__ float silu_f(float v) {
    return v / (1.f + __expf(-v));
}

// ===========================================================================
// TF32 mma.sync GEMM, ldmatrix fragment loads (register double-buffered),
// 3-stage cp.async pipeline (110.6 KB smem -> 2 CTAs/SM).   [UNCHANGED R10]
// ===========================================================================
#define T_STRIDE 36
#define NSTAGE 3
#define STAGE_ELE (2 * 128 * T_STRIDE)               // 9216 floats = 36864 B
#define GEMM_SMEM_BYTES (NSTAGE * STAGE_ELE * 4)     // 110592 B

__device__ __forceinline__ uint32_t smem_u32(const void* p) {
    uint32_t a;
    asm("{ .reg .u64 t; cvta.to.shared.u64 t, %1; cvt.u32.u64 %0, t; }"
        : "=r"(a) : "l"(p));
    return a;
}
__device__ __forceinline__ void cp16(uint32_t dst, const float* src) {
    asm volatile("cp.async.cg.shared.global [%0], [%1], 16;"
                 :: "r"(dst), "l"(src) : "memory");
}
__device__ __forceinline__ void cp_commit() {
    asm volatile("cp.async.commit_group;" ::: "memory");
}
__device__ __forceinline__ void cp_wait1() {
    asm volatile("cp.async.wait_group 1;" ::: "memory");
}
__device__ __forceinline__ void ldsm4(unsigned int* r, uint32_t addr) {
    asm volatile("ldmatrix.sync.aligned.m8n8.x4.shared.b16 {%0,%1,%2,%3}, [%4];"
                 : "=r"(r[0]), "=r"(r[1]), "=r"(r[2]), "=r"(r[3]) : "r"(addr));
}
__device__ __forceinline__ void mma_tf32(float* d, const unsigned int* a, const unsigned int* b) {
    asm volatile(
        "mma.sync.aligned.m16n8k8.row.col.f32.tf32.tf32.f32 "
        "{%0,%1,%2,%3},{%4,%5,%6,%7},{%8,%9},{%0,%1,%2,%3};"
        : "+f"(d[0]), "+f"(d[1]), "+f"(d[2]), "+f"(d[3])
        : "r"(a[0]), "r"(a[1]), "r"(a[2]), "r"(a[3]), "r"(b[0]), "r"(b[1]));
}

__global__ __launch_bounds__(256, 2)
void gemm_tf32(const float* __restrict__ Ag, const float* __restrict__ BTg,
               float* __restrict__ Cg, int M, int N, int K) {
    extern __shared__ float sm[];

    const int tid  = threadIdx.x;
    const int lane = tid & 31;
    const int warp = tid >> 5;
    const int wm   = warp >> 2;
    const int wn   = warp & 3;
    const int brow = blockIdx.y * 128;
    const int bcol = blockIdx.x * 128;

    const int lrow = tid >> 3;
    const int lc4  = (tid & 7) * 4;

    const float* Abase = Ag  + (size_t)(brow + lrow) * K + lc4;
    const float* Bbase = BTg + (size_t)(bcol + lrow) * K + lc4;

    const uint32_t smb = smem_u32(sm);
    const int nit = K >> 5;

    auto issue = [&](int t) {
        if (t < nit) {
            int st = t % NSTAGE;
            const uint32_t sb = smb + (uint32_t)st * (STAGE_ELE * 4);
            const float* Ap = Abase + t * 32;
            const float* Bp = Bbase + t * 32;
#pragma unroll
            for (int i = 0; i < 4; i++)
                cp16(sb + ((lrow + 32 * i) * T_STRIDE + lc4) * 4,
                     Ap + (size_t)(32 * i) * K);
            const uint32_t bsb = sb + 128 * T_STRIDE * 4;
#pragma unroll
            for (int i = 0; i < 4; i++)
                cp16(bsb + ((lrow + 32 * i) * T_STRIDE + lc4) * 4,
                     Bp + (size_t)(32 * i) * K);
        }
        cp_commit();
    };

    const int a_row = wm * 64 + ((lane >> 3) & 1) * 8 + (lane & 7);
    const int a_col = (lane >> 4) * 4;
    const int b_row = wn * 32 + ((lane >> 4) & 1) * 8 + (lane & 7);
    const int b_col = ((lane >> 3) & 1) * 4;

    const int lq = lane >> 2;
    const int lr = lane & 3;

    float acc[4][4][4];
#pragma unroll
    for (int mt = 0; mt < 4; mt++)
#pragma unroll
        for (int nt = 0; nt < 4; nt++)
#pragma unroll
            for (int e = 0; e < 4; e++) acc[mt][nt][e] = 0.f;

    issue(0); issue(1);

    unsigned int af[2][4][4], bf[2][2][4];

    for (int t = 0; t < nit; t++) {
        cp_wait1();
        __syncthreads();
        issue(t + 2);

        const uint32_t ab = smb + (uint32_t)(t % NSTAGE) * (STAGE_ELE * 4);
        const uint32_t bb = ab + 128 * T_STRIDE * 4;

#pragma unroll
        for (int mt = 0; mt < 4; mt++)
            ldsm4(af[0][mt], ab + ((a_row + mt * 16) * T_STRIDE + 0 + a_col) * 4);
#pragma unroll
        for (int nt2 = 0; nt2 < 2; nt2++)
            ldsm4(bf[0][nt2], bb + ((b_row + nt2 * 16) * T_STRIDE + 0 + b_col) * 4);

#pragma unroll
        for (int ks = 0; ks < 4; ks++) {
            const int cur = ks & 1;
            if (ks < 3) {
                const int k = (ks + 1) * 8;
                const int nxt = cur ^ 1;
#pragma unroll
                for (int mt = 0; mt < 4; mt++)
                    ldsm4(af[nxt][mt], ab + ((a_row + mt * 16) * T_STRIDE + k + a_col) * 4);
#pragma unroll
                for (int nt2 = 0; nt2 < 2; nt2++)
                    ldsm4(bf[nxt][nt2], bb + ((b_row + nt2 * 16) * T_STRIDE + k + b_col) * 4);
            }
#pragma unroll
            for (int mt = 0; mt < 4; mt++)
#pragma unroll
                for (int nt = 0; nt < 4; nt++)
                    mma_tf32(acc[mt][nt], af[cur][mt], &bf[cur][nt >> 1][(nt & 1) * 2]);
        }
    }

#pragma unroll
    for (int mt = 0; mt < 4; mt++) {
        const int r0 = brow + wm * 64 + mt * 16 + lq;
#pragma unroll
        for (int nt = 0; nt < 4; nt++) {
            const int c0 = bcol + wn * 32 + nt * 8 + lr * 2;
            *(float2*)&Cg[(size_t)r0 * N + c0]       = make_float2(acc[mt][nt][0], acc[mt][nt][1]);
            *(float2*)&Cg[(size_t)(r0 + 8) * N + c0] = make_float2(acc[mt][nt][2], acc[mt][nt][3]);
        }
    }
}

// ---------------------------------------------------------------------------
// Pre-passes
// ---------------------------------------------------------------------------
__global__ void round_arr(const float* __restrict__ in, float* __restrict__ out, int n) {
    int idx = blockIdx.x * blockDim.x + threadIdx.x;
    int i4 = idx * 4;
    if (i4 + 3 < n) {
        float4 v = *(const float4*)(in + i4);
        v.x = f2tf32f(v.x); v.y = f2tf32f(v.y);
        v.z = f2tf32f(v.z); v.w = f2tf32f(v.w);
        *(float4*)(out + i4) = v;
    }
}

// out[n][m] = round(in[m][n]); in is R x Cc, out is Cc x R
__global__ void transpose_round(const float* __restrict__ in, float* __restrict__ out,
                                int R, int Cc) {
    __shared__ float t[32][33];
    int bx = blockIdx.x * 32, by = blockIdx.y * 32;
#pragma unroll
    for (int j = 0; j < 32; j += 8) {
        int y = by + threadIdx.y + j, x = bx + threadIdx.x;
        t[threadIdx.y + j][threadIdx.x] = in[(size_t)y * Cc + x];
    }
    __syncthreads();
#pragma unroll
    for (int j = 0; j < 32; j += 8) {
        int y = bx + threadIdx.y + j, x = by + threadIdx.x;
        out[(size_t)y * R + x] = f2tf32f(t[threadIdx.x][threadIdx.y + j]);
    }
}

// ---------------------------------------------------------------------------
// Depthwise conv(3, pad 1) + bias + SiLU — float4 vectorized over channels.
// ---------------------------------------------------------------------------
__global__ __launch_bounds__(256)
void conv_silu(const float* __restrict__ conv_w,
               const float* __restrict__ conv_b) {
    int idx = blockIdx.x * blockDim.x + threadIdx.x;   // over NTOK*DI/4
    if (idx >= NTOK * DI / 4) return;
    const int i4 = (idx << 2) & (DI - 1);   // channel base (multiple of 4)
    const int bt = idx >> 9;                // /(DI/4)
    const int t  = bt & (SEQ - 1);

    // weights for channels i4..i4+3: conv_w[3*i4 .. 3*i4+11] = 3 float4s
    const float4 wA = *(const float4*)(conv_w + 3 * i4);     // c0:{w0,w1,w2} c1:{w0}
    const float4 wB = *(const float4*)(conv_w + 3 * i4 + 4); // c1:{w1,w2} c2:{w0,w1}
    const float4 wC = *(const float4*)(conv_w + 3 * i4 + 8); // c2:{w2} c3:{w0,w1,w2}
    const float4 bb = *(const float4*)(conv_b + i4);

    const size_t rbase = (size_t)bt * (2 * DI) + i4;
    float4 xm1 = (t > 0)       ? *(const float4*)(g_XR + rbase - 2 * DI)
                               : make_float4(0.f, 0.f, 0.f, 0.f);
    float4 x0  =                 *(const float4*)(g_XR + rbase);
    float4 xp1 = (t < SEQ - 1) ? *(const float4*)(g_XR + rbase + 2 * DI)
                               : make_float4(0.f, 0.f, 0.f, 0.f);

    float4 o;
    o.x = silu_f(fmaf(wA.x, xm1.x, fmaf(wA.y, x0.x, fmaf(wA.z, xp1.x, bb.x))));
    o.y = silu_f(fmaf(wA.w, xm1.y, fmaf(wB.x, x0.y, fmaf(wB.y, xp1.y, bb.y))));
    o.z = silu_f(fmaf(wB.z, xm1.z, fmaf(wB.w, x0.z, fmaf(wC.x, xp1.z, bb.z))));
    o.w = silu_f(fmaf(wC.y, xm1.w, fmaf(wC.z, x0.w, fmaf(wC.w, xp1.w, bb.w))));
    *(float4*)(g_XC + ((size_t)bt * DI + i4)) = o;
}

// ---------------------------------------------------------------------------
// B/C projections
// ---------------------------------------------------------------------------
__global__ __launch_bounds__(256)
void bc_gemm(const float* __restrict__ WB, const float* __restrict__ WC) {
    __shared__ float sh[32][33];
    const int row0 = blockIdx.x * 32;
    const int r = threadIdx.x & 31;
    const int g = threadIdx.x >> 5;
    const float* __restrict__ W = (g < 4) ? WB : WC;
    float* __restrict__ OUT = (g < 4) ? g_BT : g_CT;
    const int s0 = (g & 3) * 4;

    float acc[4] = {0.f, 0.f, 0.f, 0.f};
    const int lr  = threadIdx.x >> 3;
    const int lk4 = (threadIdx.x & 7) * 4;

    for (int k0 = 0; k0 < DI; k0 += 32) {
        float4 v = *(const float4*)&g_XC[(size_t)(row0 + lr) * DI + k0 + lk4];
        sh[lr][lk4 + 0] = v.x; sh[lr][lk4 + 1] = v.y;
        sh[lr][lk4 + 2] = v.z; sh[lr][lk4 + 3] = v.w;
        __syncthreads();
#pragma unroll 8
        for (int kk = 0; kk < 32; kk++) {
            float a = sh[r][kk];
            float4 w4 = *(const float4*)&W[(size_t)(k0 + kk) * DS + s0];
            acc[0] = fmaf(a, w4.x, acc[0]);
            acc[1] = fmaf(a, w4.y, acc[1]);
            acc[2] = fmaf(a, w4.z, acc[2]);
            acc[3] = fmaf(a, w4.w, acc[3]);
        }
        __syncthreads();
    }
#pragma unroll
    for (int j = 0; j < 4; j++)
        OUT[(size_t)(row0 + r) * DS + s0 + j] = acc[j];
}

// ---------------------------------------------------------------------------
// Scan (3-phase)
// ---------------------------------------------------------------------------
__global__ void scan_chunk(const float* __restrict__ A) {
    int idx = blockIdx.x * blockDim.x + threadIdx.x;
    if (idx >= BATCH * NCHUNK * DS) return;
    int s = idx & (DS - 1);
    int c = (idx >> 4) & (NCHUNK - 1);
    int b = idx >> 9;
    float d = 1.f / (1.f + expf(A[s]));
    float acc = 0.f;
    size_t base = ((size_t)b * SEQ + (size_t)c * CHUNK) * DS + s;
#pragma unroll 4
    for (int j = 0; j < CHUNK; j++)
        acc = fmaf(acc, d, g_BT[base + (size_t)j * DS]);
    g_S[idx] = acc;
}

__global__ void scan_carry(const float* __restrict__ A) {
    int idx = threadIdx.x;
    if (idx >= BATCH * DS) return;
    int s = idx & (DS - 1);
    int b = idx >> 4;
    float d = 1.f / (1.f + expf(A[s]));
    float dL = d;
#pragma unroll
    for (int q = 0; q < 7; q++) dL = dL * dL;
    float cur = 0.f;
    for (int c = 0; c < NCHUNK; c++) {
        int off = ((b * NCHUNK) + c) * DS + s;
        g_CAR[off] = cur;
        cur = fmaf(cur, dL, g_S[off]);
    }
}

__global__ void scan_ys(const float* __restrict__ A) {
    int bc = blockIdx.x;
    int b = bc >> 5, c = bc & 31;
    int lane = threadIdx.x;
    int s = lane & (DS - 1);
    float d = 1.f / (1.f + expf(A[s]));
    float state = (lane < DS) ? g_CAR[bc * DS + s] : 0.f;
    size_t base = ((size_t)b * SEQ + (size_t)c * CHUNK) * DS + s;
    int tout = b * SEQ + c * CHUNK;
    for (int j = 0; j < CHUNK; j++) {
        float v = 0.f;
        if (lane < DS) {
            size_t off = base + (size_t)j * DS;
            state = fmaf(state, d, g_BT[off]);
            v = state * g_CT[off];
        }
        v += __shfl_xor_sync(0xffffffffu, v, 8);
        v += __shfl_xor_sync(0xffffffffu, v, 4);
        v += __shfl_xor_sync(0xffffffffu, v, 2);
        v += __shfl_xor_sync(0xffffffffu, v, 1);
        if (lane == 0) g_YS[tout + j] = v;
    }
}

// ---------------------------------------------------------------------------
// Gate: Y = (ys + xc*D) * silu(res), tf32-rounded — float4 vectorized.
// ---------------------------------------------------------------------------
__global__ __launch_bounds__(256)
void ygate(const float* __restrict__ Dp) {
    int idx = blockIdx.x * blockDim.x + threadIdx.x;   // over NTOK*DI/4
    if (idx >= NTOK * DI / 4) return;
    const int i4 = (idx << 2) & (DI - 1);
    const int bt = idx >> 9;

    float4 res = *(const float4*)(g_XR + (size_t)bt * (2 * DI) + DI + i4);
    float4 xc  = *(const float4*)(g_XC + (size_t)bt * DI + i4);
    float4 dv  = *(const float4*)(Dp + i4);
    const float ys = g_YS[bt];

    float4 o;
    o.x = f2tf32f(fmaf(xc.x, dv.x, ys) * silu_f(res.x));
    o.y = f2tf32f(fmaf(xc.y, dv.y, ys) * silu_f(res.y));
    o.z = f2tf32f(fmaf(xc.z, dv.z, ys) * silu_f(res.z));
    o.w = f2tf32f(fmaf(xc.w, dv.w, ys) * silu_f(res.w));
    *(float4*)(g_Y + ((size_t)bt * DI + i4)) = o;
}

// ---------------------------------------------------------------------------
extern "C" void kernel_launch(void* const* d_in, const int* in_sizes, int n_in,
                              void* d_out, int out_size) {
    const float* x      = (const float*)d_in[0];
    const float* W_in   = (const float*)d_in[1];
    const float* conv_w = (const float*)d_in[2];
    const float* conv_b = (const float*)d_in[3];
    const float* W_B    = (const float*)d_in[4];
    const float* W_C    = (const float*)d_in[5];
    const float* A      = (const float*)d_in[6];
    const float* D      = (const float*)d_in[7];
    const float* W_out  = (const float*)d_in[8];
    float* out = (float*)d_out;

    float* XR;   cudaGetSymbolAddress((void**)&XR,   g_XR);
    float* Y;    cudaGetSymbolAddress((void**)&Y,    g_Y);
    float* Xr;   cudaGetSymbolAddress((void**)&Xr,   g_Xr);
    float* W1T;  cudaGetSymbolAddress((void**)&W1T,  g_W1T);
    float* W2T;  cudaGetSymbolAddress((void**)&W2T,  g_W2T);

    static bool attr_set = false;
    if (!attr_set) {
        cudaFuncSetAttribute(gemm_tf32, cudaFuncAttributeMaxDynamicSharedMemorySize,
                             GEMM_SMEM_BYTES);
        attr_set = true;
    }

    // 0) round x; transpose+round weights
    round_arr<<<(NTOK * DM / 4) / 256, 256>>>(x, Xr, NTOK * DM);
    {
        dim3 g((2 * DI) / 32, DM / 32);
        transpose_round<<<g, dim3(32, 8)>>>(W_in, W1T, DM, 2 * DI);
    }
    {
        dim3 g(DM / 32, DI / 32);
        transpose_round<<<g, dim3(32, 8)>>>(W_out, W2T, DI, DM);
    }

    // 1) xr = x @ W_in   (16384 x 4096 x 1024)
    {
        dim3 grid((2 * DI) / 128, NTOK / 128);
        gemm_tf32<<<grid, 256, GEMM_SMEM_BYTES>>>(Xr, W1T, XR, NTOK, 2 * DI, DM);
    }
    // 2) conv + silu (float4)
    conv_silu<<<(NTOK * DI / 4) / 256, 256>>>(conv_w, conv_b);
    // 3) B/C projections
    bc_gemm<<<NTOK / 32, 256>>>(W_B, W_C);
    // 4) scan
    scan_chunk<<<(BATCH * NCHUNK * DS + 255) / 256, 256>>>(A);
    scan_carry<<<1, 64>>>(A);
    scan_ys<<<BATCH * NCHUNK, 32>>>(A);
    // 5) gate (float4)
    ygate<<<(NTOK * DI / 4) / 256, 256>>>(D);
    // 6) out = Y @ W_out   (16384 x 1024 x 2048)
    {
        dim3 grid(DM / 128, NTOK / 128);
        gemm_tf32<<<grid, 256, GEMM_SMEM_BYTES>>>(Y, W2T, out, NTOK, DM, DI);
    }
}